// round 12
// baseline (speedup 1.0000x reference)
#include <cuda_runtime.h>
#include <math.h>

typedef unsigned long long ull;
typedef unsigned int u32;

// ---------------------------------------------------------------- constants
#define NB   64
#define NS   512
#define NH   512
#define NA   512
#define NCC  4
#define NV   1000
#define NED  128
#define NFF  6
#define BS   32768          // NB*NS

// ---------------------------------------------------------------- scratch
__device__ float g_CE[BS * NH];       // scores
__device__ float g_X [BS * NH];       // x
__device__ float g_Q [BS * NA];       // Q; reused as Zt
__device__ float g_K [BS * NA];       // K; reused as H0 (layer-0 output)
__device__ float g_V [BS * NA];       // V; reused as H1 (layer-1 output)
__device__ float g_GI[BS * 3 * NA];   // GRU input gates (per layer)
__device__ float g_Wcc[NFF * NH];
__device__ float g_bcc[NH];
__device__ u32   g_gc[256];           // per-group arrival counters (stride 32)

// ---------------------------------------------------------------- helpers
__device__ __forceinline__ float sigm(float x) { return 1.f / (1.f + expf(-x)); }
__device__ __forceinline__ u32 f2tf(float x) {
    u32 r; asm("cvt.rna.tf32.f32 %0,%1;" : "=r"(r) : "f"(x)); return r;
}
__device__ __forceinline__ void cpa16(u32 dst, const void* src) {
    asm volatile("cp.async.cg.shared.global [%0], [%1], 16;" :: "r"(dst), "l"(src));
}
__device__ __forceinline__ u32 cvsm(const void* p) {
    u32 r;
    asm("{ .reg .u64 t; cvta.to.shared.u64 t, %1; cvt.u32.u64 %0, t; }" : "=r"(r) : "l"(p));
    return r;
}

// ---------------------------------------------------------------- prep
__global__ void k_prep(const float* __restrict__ Wcont, const float* __restrict__ bcont,
                       const float* __restrict__ Wcomb, const float* __restrict__ bcomb) {
    int j = blockIdx.x * 256 + threadIdx.x;
    if (j >= NH) return;
    float acc[NFF];
#pragma unroll
    for (int f = 0; f < NFF; f++) acc[f] = 0.f;
    float bacc = bcomb[j];
    for (int m = 0; m < NH; m++) {
        float w2 = Wcomb[(NH + m) * NH + j];
        bacc += bcont[m] * w2;
#pragma unroll
        for (int f = 0; f < NFF; f++) acc[f] += Wcont[f * NH + m] * w2;
    }
#pragma unroll
    for (int f = 0; f < NFF; f++) g_Wcc[f * NH + j] = acc[f];
    g_bcc[j] = bacc;
}

// ---------------------------------------------------------------- pipelined tf32 GEMM, 128x128 tile
// C[M,N] = scale*(A @ op(B)) + bias; BK=32, 3-stage cp.async, raw fp32 bits as tf32.
// EXTRAS: fuse pos-enc + cont-term + bcc into epilogue (combine GEMM only).
#define ASZ 4608                 // 128*36 u32
#define BSZ 4608                 // max(32*136, 128*36)
#define STGSZ (ASZ + BSZ)
#define GEMM_SMEM (3 * STGSZ * 4)

template <int TRB, int GATHER>
__device__ __forceinline__ void g_load_stage(
    u32 smb, int st, const float* A, const float* Bm,
    const int* cate, const float* emb,
    int m0, int n0, int k0, int N, int K, int t) {
    u32 ab = smb + st * (STGSZ * 4);
#pragma unroll
    for (int rr = 0; rr < 4; rr++) {
        int q = t + rr * 256;
        int m = q >> 3, kc = q & 7;
        const float* src;
        if (GATHER) {
            int k = k0 + kc * 4;
            int cf = k >> 7, e = k & 127;
            int idx = __ldg(cate + (m0 + m) * NCC + cf);
            src = emb + ((long)cf * NV + idx) * NED + e;
        } else {
            src = A + (long)(m0 + m) * K + k0 + kc * 4;
        }
        cpa16(ab + (m * 36 + kc * 4) * 4, src);
    }
    u32 bb = ab + ASZ * 4;
#pragma unroll
    for (int rr = 0; rr < 4; rr++) {
        int q = t + rr * 256;
        if (TRB == 0) {
            int k = q >> 5, nc = q & 31;
            cpa16(bb + (k * 136 + nc * 4) * 4, Bm + (long)(k0 + k) * N + n0 + nc * 4);
        } else {
            int n = q >> 3, kc = q & 7;
            cpa16(bb + (n * 36 + kc * 4) * 4, Bm + (long)(n0 + n) * K + k0 + kc * 4);
        }
    }
}

template <int TRB, int GATHER, int EXTRAS>
__global__ __launch_bounds__(256, 2) void k_tgemm(
    const float* __restrict__ A, const float* __restrict__ Bm, float* __restrict__ C,
    int N, int K, long sA, long sB, long sC, long ldc,
    const float* __restrict__ bias, float scale,
    const int* __restrict__ cate, const float* __restrict__ emb,
    const float* __restrict__ cont) {
    extern __shared__ u32 smp[];
    u32 smb = cvsm(smp);

    A  += (long)blockIdx.z * sA;
    Bm += (long)blockIdx.z * sB;
    C  += (long)blockIdx.z * sC;
    int m0 = blockIdx.y * 128, n0 = blockIdx.x * 128;
    int t = threadIdx.x;
    int warp = t >> 5, lane = t & 31;
    int wm = (warp >> 2) * 64;
    int wn = (warp & 3) * 32;
    int r = lane >> 2, c = lane & 3;

    float acc[4][4][4];
#pragma unroll
    for (int mt = 0; mt < 4; mt++)
#pragma unroll
        for (int nt = 0; nt < 4; nt++)
#pragma unroll
            for (int i = 0; i < 4; i++) acc[mt][nt][i] = 0.f;

    int niter = K >> 5;
    g_load_stage<TRB, GATHER>(smb, 0, A, Bm, cate, emb, m0, n0, 0, N, K, t);
    asm volatile("cp.async.commit_group;");
    g_load_stage<TRB, GATHER>(smb, 1, A, Bm, cate, emb, m0, n0, 32, N, K, t);
    asm volatile("cp.async.commit_group;");

    for (int i = 0; i < niter; i++) {
        if (i == niter - 1) asm volatile("cp.async.wait_group 0;");
        else                asm volatile("cp.async.wait_group 1;");
        __syncthreads();
        if (i + 2 < niter) {
            g_load_stage<TRB, GATHER>(smb, (i + 2) % 3, A, Bm, cate, emb,
                                      m0, n0, (i + 2) * 32, N, K, t);
            asm volatile("cp.async.commit_group;");
        }
        const u32* As_ = smp + (i % 3) * STGSZ;
        const u32* Bs_ = As_ + ASZ;
#pragma unroll
        for (int kb = 0; kb < 32; kb += 8) {
            u32 a[4][4];
#pragma unroll
            for (int mt = 0; mt < 4; mt++) {
                int row = wm + mt * 16 + r;
                a[mt][0] = As_[row * 36 + kb + c];
                a[mt][1] = As_[(row + 8) * 36 + kb + c];
                a[mt][2] = As_[row * 36 + kb + c + 4];
                a[mt][3] = As_[(row + 8) * 36 + kb + c + 4];
            }
#pragma unroll
            for (int nt = 0; nt < 4; nt++) {
                int col = wn + nt * 8 + r;
                u32 b0, b1;
                if (TRB == 0) {
                    b0 = Bs_[(kb + c) * 136 + col];
                    b1 = Bs_[(kb + c + 4) * 136 + col];
                } else {
                    b0 = Bs_[col * 36 + kb + c];
                    b1 = Bs_[col * 36 + kb + c + 4];
                }
#pragma unroll
                for (int mt = 0; mt < 4; mt++) {
                    asm volatile(
                        "mma.sync.aligned.m16n8k8.row.col.f32.tf32.tf32.f32 "
                        "{%0,%1,%2,%3},{%4,%5,%6,%7},{%8,%9},{%0,%1,%2,%3};"
                        : "+f"(acc[mt][nt][0]), "+f"(acc[mt][nt][1]),
                          "+f"(acc[mt][nt][2]), "+f"(acc[mt][nt][3])
                        : "r"(a[mt][0]), "r"(a[mt][1]), "r"(a[mt][2]), "r"(a[mt][3]),
                          "r"(b0), "r"(b1));
                }
            }
        }
    }
#pragma unroll
    for (int mt = 0; mt < 4; mt++) {
#pragma unroll
        for (int nt = 0; nt < 4; nt++) {
            int row = m0 + wm + mt * 16 + r;
            int col = n0 + wn + nt * 8 + c * 2;
            float bb0 = 0.f, bb1 = 0.f;
            if (bias) { bb0 = __ldg(bias + col); bb1 = __ldg(bias + col + 1); }
            float2 lo = make_float2(acc[mt][nt][0] * scale + bb0,
                                    acc[mt][nt][1] * scale + bb1);
            float2 hi = make_float2(acc[mt][nt][2] * scale + bb0,
                                    acc[mt][nt][3] * scale + bb1);
            if (EXTRAS) {
                // pos-enc + cont@Wcc + bcc, matching the standalone extras kernel
                int sr0 = row & 511, sr1 = (row + 8) & 511;
                float kf = expf(-(float)col * 0.0179889460f);   // ln(10000)/512
                float s0, c0, s1, c1;
                sincosf((float)sr0 * kf, &s0, &c0);
                sincosf((float)sr1 * kf, &s1, &c1);
                float bc0 = g_bcc[col], bc1 = g_bcc[col + 1];
                float ct0 = 0.f, ct1 = 0.f, ct0b = 0.f, ct1b = 0.f;
#pragma unroll
                for (int f = 0; f < NFF; f++) {
                    float w0 = g_Wcc[f * NH + col], w1 = g_Wcc[f * NH + col + 1];
                    float cr0 = __ldg(cont + (long)row * NFF + f);
                    float cr1 = __ldg(cont + (long)(row + 8) * NFF + f);
                    ct0 += cr0 * w0;  ct1 += cr0 * w1;
                    ct0b += cr1 * w0; ct1b += cr1 * w1;
                }
                lo.x += bc0 + ct0 + s0;  lo.y += bc1 + ct1 + c0;
                hi.x += bc0 + ct0b + s1; hi.y += bc1 + ct1b + c1;
            }
            *(float2*)(C + (long)row * ldc + col) = lo;
            *(float2*)(C + (long)(row + 8) * ldc + col) = hi;
        }
    }
}

// ---------------------------------------------------------------- softmax over q (axis=1), smem-staged
#define SMX_STR 72
#define SMX_SMEM ((512 * SMX_STR + 256) * 4)

__global__ __launch_bounds__(256) void k_softmax(float* __restrict__ P) {
    extern __shared__ float sx[];
    float* red = sx + 512 * SMX_STR;
    int b = blockIdx.y, k0 = blockIdx.x * 64;
    int t = threadIdx.x;
    float* base = P + (long)b * (NS * NS) + k0;

#pragma unroll
    for (int i = 0; i < 32; i++) {
        int q = i * 16 + (t >> 4), c4 = (t & 15) * 4;
        float4 v = *(const float4*)(base + (long)q * NS + c4);
        *(float4*)&sx[q * SMX_STR + c4] = v;
    }
    __syncthreads();

    int tc = t & 63, tq = t >> 6;
    float m = -1e30f;
#pragma unroll 8
    for (int q = tq * 128; q < tq * 128 + 128; q++) m = fmaxf(m, sx[q * SMX_STR + tc]);
    red[t] = m;
    __syncthreads();
    if (t < 64) red[t] = fmaxf(fmaxf(red[t], red[64 + t]), fmaxf(red[128 + t], red[192 + t]));
    __syncthreads();
    m = red[tc];
    __syncthreads();
    float s = 0.f;
#pragma unroll 8
    for (int q = tq * 128; q < tq * 128 + 128; q++) {
        float e = __expf(sx[q * SMX_STR + tc] - m);
        sx[q * SMX_STR + tc] = e;
        s += e;
    }
    red[t] = s;
    __syncthreads();
    if (t < 64) red[t] = (red[t] + red[64 + t]) + (red[128 + t] + red[192 + t]);
    __syncthreads();
    float inv = 1.f / red[tc];
#pragma unroll 8
    for (int q = tq * 128; q < tq * 128 + 128; q++)
        base[(long)q * NS + tc] = sx[q * SMX_STR + tc] * inv;
}

// ---------------------------------------------------------------- reset counters
__global__ void k_rst() { g_gc[threadIdx.x] = 0; }

// ---------------------------------------------------------------- batch-grouped persistent GRU
// 128 CTAs = 8 groups x 16 CTAs. Group g owns batches 8g..8g+7.
// CTA owns 32 units x 3 gates = 96 Wh rows, pre-swizzled tf32 A-fragments in SMEM.
// h_prev staged from Hout[s-1] via cp.async (no separate double buffer).
#define HSTR 516
#define WS_U32 (6 * 64 * 32 * 4)
#define GRU_SMEM ((WS_U32 + 8 * HSTR + 96 * 11) * 4)

__global__ __launch_bounds__(256) void k_gru(const float* __restrict__ GI,
                                             const float* __restrict__ Wh,
                                             const float* __restrict__ bh,
                                             float* __restrict__ Hout) {
    extern __shared__ float sm[];
    u32*   ws = (u32*)sm;
    float* hs = sm + WS_U32;
    float* ps = sm + WS_U32 + 8 * HSTR;
    const u32* hsu = (const u32*)hs;
    u32 hsaddr = cvsm(hs);

    int t = threadIdx.x;
    int w = t >> 5, l = t & 31;
    int r = l >> 2, c = l & 3;
    int grp = blockIdx.x >> 4;
    int cig = blockIdx.x & 15;
    int u0  = cig * 32;
    int bg0 = grp * 8;
    volatile u32* bar = &g_gc[grp * 32];

    for (int idx = t; idx < 6 * 64 * 32; idx += 256) {
        int lane = idx & 31, mtks = idx >> 5;
        int mt = mtks % 6, ks = mtks / 6;
        int rr = lane >> 2, cc = lane & 3;
        int j0 = mt * 16 + rr, j1 = j0 + 8;
        int k0 = ks * 8 + cc, k1 = k0 + 4;
        long row0 = (long)((j0 >> 5) * NA + u0 + (j0 & 31)) * NA;
        long row1 = (long)((j1 >> 5) * NA + u0 + (j1 & 31)) * NA;
        uint4 v;
        v.x = f2tf(Wh[row0 + k0]);
        v.y = f2tf(Wh[row1 + k0]);
        v.z = f2tf(Wh[row0 + k1]);
        v.w = f2tf(Wh[row1 + k1]);
        *(uint4*)&ws[((ks * 6 + mt) * 32 + lane) * 4] = v;
    }

    int cb = t >> 5, cu = t & 31;
    int u = u0 + cu;
    float bhr = bh[u], bhz = bh[NA + u], bhn = bh[2 * NA + u];
    __syncthreads();

    for (int s = 0; s < NS; s++) {
        // GI prefetch (independent of recurrence)
        const float* gi = GI + ((long)s * NB + bg0 + cb) * (3 * NA) + u;
        float gr = __ldg(gi), gz = __ldg(gi + NA), gn = __ldg(gi + 2 * NA);

        // wait for all 16 group CTAs to finish step s-1
        if (s > 0) {
            if (t == 0) {
                u32 need = (u32)(16 * s);
                while (*bar < need) { }
                __threadfence();
            }
            __syncthreads();
        }

        // stage h_prev from Hout[s-1] (cp.async, coalesced)
        if (s == 0) {
            float4 zz = make_float4(0.f, 0.f, 0.f, 0.f);
#pragma unroll
            for (int i = 0; i < 4; i++) {
                int g = t + i * 256;
                *(float4*)&hs[(g >> 7) * HSTR + (g & 127) * 4] = zz;
            }
        } else {
            const float* hb = Hout + ((long)(s - 1) * NB + bg0) * NA;
#pragma unroll
            for (int i = 0; i < 4; i++) {
                int g = t + i * 256;
                cpa16(hsaddr + ((g >> 7) * HSTR + (g & 127) * 4) * 4,
                      hb + (g >> 7) * NA + (g & 127) * 4);
            }
            asm volatile("cp.async.commit_group;");
            asm volatile("cp.async.wait_group 0;");
        }
        __syncthreads();

        // mma: warps 0-5, one 16-row m-tile each, N=8, K=512
        if (w < 6) {
            float a0 = 0.f, a1 = 0.f, a2 = 0.f, a3 = 0.f;
#pragma unroll 8
            for (int ks = 0; ks < 64; ks++) {
                uint4 af = *(const uint4*)&ws[((ks * 6 + w) * 32 + l) * 4];
                u32 b0 = hsu[r * HSTR + ks * 8 + c];
                u32 b1 = hsu[r * HSTR + ks * 8 + c + 4];
                asm volatile(
                    "mma.sync.aligned.m16n8k8.row.col.f32.tf32.tf32.f32 "
                    "{%0,%1,%2,%3},{%4,%5,%6,%7},{%8,%9},{%0,%1,%2,%3};"
                    : "+f"(a0), "+f"(a1), "+f"(a2), "+f"(a3)
                    : "r"(af.x), "r"(af.y), "r"(af.z), "r"(af.w),
                      "r"(b0), "r"(b1));
            }
            int row = w * 16 + r;
            ps[row * 11 + c * 2]           = a0;
            ps[row * 11 + c * 2 + 1]       = a1;
            ps[(row + 8) * 11 + c * 2]     = a2;
            ps[(row + 8) * 11 + c * 2 + 1] = a3;
        }
        __syncthreads();

        // gate combine (batch cb, unit cu)
        float ar = ps[cu * 11 + cb];
        float az = ps[(32 + cu) * 11 + cb];
        float an = ps[(64 + cu) * 11 + cb];
        float rg = sigm(gr + ar + bhr);
        float zg = sigm(gz + az + bhz);
        float ng = tanhf(gn + rg * (an + bhn));
        float hp = hs[cb * HSTR + u];
        float hval = (1.f - zg) * ng + zg * hp;
        Hout[((long)s * NB + bg0 + cb) * NA + u] = hval;
        __syncthreads();
        if (t == 0) { __threadfence(); atomicAdd((u32*)&g_gc[grp * 32], 1u); }
    }
}

// ---------------------------------------------------------------- head
__global__ void k_head(const float* __restrict__ Hs, const float* __restrict__ Wf,
                       const float* __restrict__ bf, float* __restrict__ out) {
    int warp = (blockIdx.x * 256 + threadIdx.x) >> 5;
    int lane = threadIdx.x & 31;
    const float* row = Hs + (long)warp * NA;
    float s = 0.f;
#pragma unroll
    for (int i = 0; i < 16; i++) s += row[lane + i * 32] * __ldg(&Wf[lane + i * 32]);
#pragma unroll
    for (int o = 16; o; o >>= 1) s += __shfl_xor_sync(0xffffffffu, s, o);
    if (lane == 0) {
        int ss = warp >> 6, b = warp & 63;
        out[b * NS + ss] = sigm(s + __ldg(bf));
    }
}

// ---------------------------------------------------------------- launch
extern "C" void kernel_launch(void* const* d_in, const int* in_sizes, int n_in,
                              void* d_out, int out_size) {
    const int*   cate  = (const int*)d_in[0];
    const float* cont  = (const float*)d_in[1];
    const float* emb   = (const float*)d_in[4];
    const float* Wcont = (const float*)d_in[5];
    const float* bcont = (const float*)d_in[6];
    const float* Wcomb = (const float*)d_in[7];
    const float* bcomb = (const float*)d_in[8];
    const float* Wq    = (const float*)d_in[9];
    const float* Wk    = (const float*)d_in[10];
    const float* Wv    = (const float*)d_in[11];
    const float* Wi    = (const float*)d_in[12];
    const float* Wh    = (const float*)d_in[13];
    const float* bi    = (const float*)d_in[14];
    const float* bh    = (const float*)d_in[15];
    const float* Wfin  = (const float*)d_in[16];
    const float* bfin  = (const float*)d_in[17];
    float* out = (float*)d_out;

    float *CE, *X, *Q, *K, *V, *GI;
    cudaGetSymbolAddress((void**)&CE, g_CE);
    cudaGetSymbolAddress((void**)&X,  g_X);
    cudaGetSymbolAddress((void**)&Q,  g_Q);
    cudaGetSymbolAddress((void**)&K,  g_K);
    cudaGetSymbolAddress((void**)&V,  g_V);
    cudaGetSymbolAddress((void**)&GI, g_GI);

    cudaFuncSetAttribute(k_gru, cudaFuncAttributeMaxDynamicSharedMemorySize, GRU_SMEM);
    cudaFuncSetAttribute(k_tgemm<0, 0, 0>, cudaFuncAttributeMaxDynamicSharedMemorySize, GEMM_SMEM);
    cudaFuncSetAttribute(k_tgemm<1, 0, 0>, cudaFuncAttributeMaxDynamicSharedMemorySize, GEMM_SMEM);
    cudaFuncSetAttribute(k_tgemm<0, 1, 1>, cudaFuncAttributeMaxDynamicSharedMemorySize, GEMM_SMEM);
    cudaFuncSetAttribute(k_softmax, cudaFuncAttributeMaxDynamicSharedMemorySize, SMX_SMEM);

    const long SB2 = (long)NS * NS;
    const float iscl = 0.0441941738241592f; // 1/sqrt(512)

    k_prep<<<2, 256>>>(Wcont, bcont, Wcomb, bcomb);
    // x = gather(emb, cate) @ Wcomb[0:512]  + extras fused into epilogue
    k_tgemm<0, 1, 1><<<dim3(4, 256, 1), 256, GEMM_SMEM>>>(
        nullptr, Wcomb, X, NH, NH, 0, 0, 0, NH, nullptr, 1.f, cate, emb, cont);
    // QKV
    k_tgemm<0, 0, 0><<<dim3(4, 256, 1), 256, GEMM_SMEM>>>(
        X, Wq, Q, NA, NH, 0, 0, 0, NA, nullptr, 1.f, nullptr, nullptr, nullptr);
    k_tgemm<0, 0, 0><<<dim3(4, 256, 1), 256, GEMM_SMEM>>>(
        X, Wk, K, NA, NH, 0, 0, 0, NA, nullptr, 1.f, nullptr, nullptr, nullptr);
    k_tgemm<0, 0, 0><<<dim3(4, 256, 1), 256, GEMM_SMEM>>>(
        X, Wv, V, NA, NH, 0, 0, 0, NA, nullptr, 1.f, nullptr, nullptr, nullptr);
    // scores = Q @ K^T / sqrt(A)
    k_tgemm<1, 0, 0><<<dim3(4, 4, 64), 256, GEMM_SMEM>>>(
        Q, K, CE, NS, NA, SB2, SB2, SB2, NS, nullptr, iscl, nullptr, nullptr, nullptr);
    k_softmax<<<dim3(8, 64), 256, SMX_SMEM>>>(CE);
    // Zt[(s,b),:] = (P @ V)[b,s,:]  — transpose fused via ldc/sC
    k_tgemm<0, 0, 0><<<dim3(4, 4, 64), 256, GEMM_SMEM>>>(
        CE, V, Q, NA, NS, SB2, SB2, (long)NA, (long)NB * NA, nullptr, 1.f,
        nullptr, nullptr, nullptr);
    // layer 0
    k_tgemm<1, 0, 0><<<dim3(12, 256, 1), 256, GEMM_SMEM>>>(
        Q, Wi, GI, 3 * NA, NA, 0, 0, 0, 3 * NA, bi, 1.f, nullptr, nullptr, nullptr);
    k_rst<<<1, 256>>>();
    k_gru<<<128, 256, GRU_SMEM>>>(GI, Wh, bh, K);
    // layer 1
    k_tgemm<1, 0, 0><<<dim3(12, 256, 1), 256, GEMM_SMEM>>>(
        K, Wi + 3 * NA * NA, GI, 3 * NA, NA, 0, 0, 0, 3 * NA, bi + 3 * NA, 1.f,
        nullptr, nullptr, nullptr);
    k_rst<<<1, 256>>>();
    k_gru<<<128, 256, GRU_SMEM>>>(GI, Wh + 3 * NA * NA, bh + 3 * NA, V);
    // head
    k_head<<<BS / 8, 256>>>(V, Wfin, bfin, out);
}

// round 13
// speedup vs baseline: 1.1243x; 1.1243x over previous
#include <cuda_runtime.h>
#include <math.h>

typedef unsigned long long ull;
typedef unsigned int u32;

// ---------------------------------------------------------------- constants
#define NB   64
#define NS   512
#define NH   512
#define NA   512
#define NCC  4
#define NV   1000
#define NED  128
#define NFF  6
#define BS   32768          // NB*NS

// ---------------------------------------------------------------- scratch
__device__ float g_CE[BS * NH];       // scores
__device__ float g_X [BS * NH];       // x
__device__ float g_Q [BS * NA];       // Q; reused as Zt
__device__ float g_K [BS * NA];       // K; reused as H0 (layer-0 output)
__device__ float g_V [BS * NA];       // V; reused as H1 (layer-1 output)
__device__ float g_GI[BS * 3 * NA];   // GRU input gates (per layer)
__device__ float g_Wcc[NFF * NH];
__device__ float g_bcc[NH];
__device__ u32   g_gc[256];           // per-group arrival counters (stride 32)

// ---------------------------------------------------------------- helpers
__device__ __forceinline__ float sigm(float x) { return 1.f / (1.f + expf(-x)); }
__device__ __forceinline__ u32 f2tf(float x) {
    u32 r; asm("cvt.rna.tf32.f32 %0,%1;" : "=r"(r) : "f"(x)); return r;
}
__device__ __forceinline__ void cpa16(u32 dst, const void* src) {
    asm volatile("cp.async.cg.shared.global [%0], [%1], 16;" :: "r"(dst), "l"(src));
}
__device__ __forceinline__ u32 cvsm(const void* p) {
    u32 r;
    asm("{ .reg .u64 t; cvta.to.shared.u64 t, %1; cvt.u32.u64 %0, t; }" : "=r"(r) : "l"(p));
    return r;
}

// ---------------------------------------------------------------- prep
__global__ void k_prep(const float* __restrict__ Wcont, const float* __restrict__ bcont,
                       const float* __restrict__ Wcomb, const float* __restrict__ bcomb) {
    int j = blockIdx.x * 256 + threadIdx.x;
    if (j >= NH) return;
    float acc[NFF];
#pragma unroll
    for (int f = 0; f < NFF; f++) acc[f] = 0.f;
    float bacc = bcomb[j];
    for (int m = 0; m < NH; m++) {
        float w2 = Wcomb[(NH + m) * NH + j];
        bacc += bcont[m] * w2;
#pragma unroll
        for (int f = 0; f < NFF; f++) acc[f] += Wcont[f * NH + m] * w2;
    }
#pragma unroll
    for (int f = 0; f < NFF; f++) g_Wcc[f * NH + j] = acc[f];
    g_bcc[j] = bacc;
}

// ---------------------------------------------------------------- pipelined tf32 GEMM, 128x128 tile
// C[M,N] = scale*(A @ op(B)) + bias; BK=32, 3-stage cp.async, raw fp32 bits as tf32.
// Fragment feeds via ldmatrix (A always; B in TRB=1). EXTRAS fuses pos-enc/cont into epilogue.
#define ASZ 4608                 // 128*36 u32
#define BSZ 4608                 // max(32*136, 128*36)
#define STGSZ (ASZ + BSZ)
#define GEMM_SMEM (3 * STGSZ * 4)

template <int TRB, int GATHER>
__device__ __forceinline__ void g_load_stage(
    u32 smb, int st, const float* A, const float* Bm,
    const int* cate, const float* emb,
    int m0, int n0, int k0, int N, int K, int t) {
    u32 ab = smb + st * (STGSZ * 4);
#pragma unroll
    for (int rr = 0; rr < 4; rr++) {
        int q = t + rr * 256;
        int m = q >> 3, kc = q & 7;
        const float* src;
        if (GATHER) {
            int k = k0 + kc * 4;
            int cf = k >> 7, e = k & 127;
            int idx = __ldg(cate + (m0 + m) * NCC + cf);
            src = emb + ((long)cf * NV + idx) * NED + e;
        } else {
            src = A + (long)(m0 + m) * K + k0 + kc * 4;
        }
        cpa16(ab + (m * 36 + kc * 4) * 4, src);
    }
    u32 bb = ab + ASZ * 4;
#pragma unroll
    for (int rr = 0; rr < 4; rr++) {
        int q = t + rr * 256;
        if (TRB == 0) {
            int k = q >> 5, nc = q & 31;
            cpa16(bb + (k * 136 + nc * 4) * 4, Bm + (long)(k0 + k) * N + n0 + nc * 4);
        } else {
            int n = q >> 3, kc = q & 7;
            cpa16(bb + (n * 36 + kc * 4) * 4, Bm + (long)(n0 + n) * K + k0 + kc * 4);
        }
    }
}

template <int TRB, int GATHER, int EXTRAS>
__global__ __launch_bounds__(256, 2) void k_tgemm(
    const float* __restrict__ A, const float* __restrict__ Bm, float* __restrict__ C,
    int N, int K, long sA, long sB, long sC, long ldc,
    const float* __restrict__ bias, float scale,
    const int* __restrict__ cate, const float* __restrict__ emb,
    const float* __restrict__ cont) {
    extern __shared__ u32 smp[];
    u32 smb = cvsm(smp);

    A  += (long)blockIdx.z * sA;
    Bm += (long)blockIdx.z * sB;
    C  += (long)blockIdx.z * sC;
    int m0 = blockIdx.y * 128, n0 = blockIdx.x * 128;
    int t = threadIdx.x;
    int warp = t >> 5, lane = t & 31;
    int wm = (warp >> 2) * 64;
    int wn = (warp & 3) * 32;
    int r = lane >> 2, c = lane & 3;
    int la = lane & 15, lh = lane >> 4;   // ldmatrix A addressing
    int lb = lane & 15;                    // ldmatrix B addressing (x2)

    float acc[4][4][4];
#pragma unroll
    for (int mt = 0; mt < 4; mt++)
#pragma unroll
        for (int nt = 0; nt < 4; nt++)
#pragma unroll
            for (int i = 0; i < 4; i++) acc[mt][nt][i] = 0.f;

    int niter = K >> 5;
    g_load_stage<TRB, GATHER>(smb, 0, A, Bm, cate, emb, m0, n0, 0, N, K, t);
    asm volatile("cp.async.commit_group;");
    g_load_stage<TRB, GATHER>(smb, 1, A, Bm, cate, emb, m0, n0, 32, N, K, t);
    asm volatile("cp.async.commit_group;");

    for (int i = 0; i < niter; i++) {
        if (i == niter - 1) asm volatile("cp.async.wait_group 0;");
        else                asm volatile("cp.async.wait_group 1;");
        __syncthreads();
        if (i + 2 < niter) {
            g_load_stage<TRB, GATHER>(smb, (i + 2) % 3, A, Bm, cate, emb,
                                      m0, n0, (i + 2) * 32, N, K, t);
            asm volatile("cp.async.commit_group;");
        }
        u32 As_base = smb + (u32)((i % 3) * STGSZ * 4);
        u32 Bs_base = As_base + ASZ * 4;
        const u32* Bs_ = smp + (i % 3) * STGSZ + ASZ;
#pragma unroll
        for (int kb = 0; kb < 32; kb += 8) {
            u32 a[4][4];
#pragma unroll
            for (int mt = 0; mt < 4; mt++) {
                u32 aaddr = As_base + (u32)(((wm + mt * 16 + la) * 36 + kb + lh * 4) * 4);
                asm volatile(
                    "ldmatrix.sync.aligned.m8n8.x4.shared.b16 {%0,%1,%2,%3},[%4];"
                    : "=r"(a[mt][0]), "=r"(a[mt][1]), "=r"(a[mt][2]), "=r"(a[mt][3])
                    : "r"(aaddr));
            }
#pragma unroll
            for (int nt = 0; nt < 4; nt++) {
                u32 b0, b1;
                if (TRB == 0) {
                    int col = wn + nt * 8 + r;
                    b0 = Bs_[(kb + c) * 136 + col];
                    b1 = Bs_[(kb + c + 4) * 136 + col];
                } else {
                    u32 baddr = Bs_base +
                        (u32)(((wn + nt * 8 + (lb & 7)) * 36 + kb + (lb >> 3) * 4) * 4);
                    asm volatile(
                        "ldmatrix.sync.aligned.m8n8.x2.shared.b16 {%0,%1},[%2];"
                        : "=r"(b0), "=r"(b1) : "r"(baddr));
                }
#pragma unroll
                for (int mt = 0; mt < 4; mt++) {
                    asm volatile(
                        "mma.sync.aligned.m16n8k8.row.col.f32.tf32.tf32.f32 "
                        "{%0,%1,%2,%3},{%4,%5,%6,%7},{%8,%9},{%0,%1,%2,%3};"
                        : "+f"(acc[mt][nt][0]), "+f"(acc[mt][nt][1]),
                          "+f"(acc[mt][nt][2]), "+f"(acc[mt][nt][3])
                        : "r"(a[mt][0]), "r"(a[mt][1]), "r"(a[mt][2]), "r"(a[mt][3]),
                          "r"(b0), "r"(b1));
                }
            }
        }
    }
#pragma unroll
    for (int mt = 0; mt < 4; mt++) {
#pragma unroll
        for (int nt = 0; nt < 4; nt++) {
            int row = m0 + wm + mt * 16 + r;
            int col = n0 + wn + nt * 8 + c * 2;
            float bb0 = 0.f, bb1 = 0.f;
            if (bias) { bb0 = __ldg(bias + col); bb1 = __ldg(bias + col + 1); }
            float2 lo = make_float2(acc[mt][nt][0] * scale + bb0,
                                    acc[mt][nt][1] * scale + bb1);
            float2 hi = make_float2(acc[mt][nt][2] * scale + bb0,
                                    acc[mt][nt][3] * scale + bb1);
            if (EXTRAS) {
                int sr0 = row & 511, sr1 = (row + 8) & 511;
                float kf = expf(-(float)col * 0.0179889460f);   // ln(10000)/512
                float s0, c0, s1, c1;
                sincosf((float)sr0 * kf, &s0, &c0);
                sincosf((float)sr1 * kf, &s1, &c1);
                float bc0 = g_bcc[col], bc1 = g_bcc[col + 1];
                float ct0 = 0.f, ct1 = 0.f, ct0b = 0.f, ct1b = 0.f;
#pragma unroll
                for (int f = 0; f < NFF; f++) {
                    float w0 = g_Wcc[f * NH + col], w1 = g_Wcc[f * NH + col + 1];
                    float cr0 = __ldg(cont + (long)row * NFF + f);
                    float cr1 = __ldg(cont + (long)(row + 8) * NFF + f);
                    ct0 += cr0 * w0;  ct1 += cr0 * w1;
                    ct0b += cr1 * w0; ct1b += cr1 * w1;
                }
                lo.x += bc0 + ct0 + s0;  lo.y += bc1 + ct1 + c0;
                hi.x += bc0 + ct0b + s1; hi.y += bc1 + ct1b + c1;
            }
            *(float2*)(C + (long)row * ldc + col) = lo;
            *(float2*)(C + (long)(row + 8) * ldc + col) = hi;
        }
    }
}

// ---------------------------------------------------------------- softmax over q (axis=1), smem-staged
#define SMX_STR 72
#define SMX_SMEM ((512 * SMX_STR + 256) * 4)

__global__ __launch_bounds__(256) void k_softmax(float* __restrict__ P) {
    extern __shared__ float sx[];
    float* red = sx + 512 * SMX_STR;
    int b = blockIdx.y, k0 = blockIdx.x * 64;
    int t = threadIdx.x;
    float* base = P + (long)b * (NS * NS) + k0;

#pragma unroll
    for (int i = 0; i < 32; i++) {
        int q = i * 16 + (t >> 4), c4 = (t & 15) * 4;
        float4 v = *(const float4*)(base + (long)q * NS + c4);
        *(float4*)&sx[q * SMX_STR + c4] = v;
    }
    __syncthreads();

    int tc = t & 63, tq = t >> 6;
    float m = -1e30f;
#pragma unroll 8
    for (int q = tq * 128; q < tq * 128 + 128; q++) m = fmaxf(m, sx[q * SMX_STR + tc]);
    red[t] = m;
    __syncthreads();
    if (t < 64) red[t] = fmaxf(fmaxf(red[t], red[64 + t]), fmaxf(red[128 + t], red[192 + t]));
    __syncthreads();
    m = red[tc];
    __syncthreads();
    float s = 0.f;
#pragma unroll 8
    for (int q = tq * 128; q < tq * 128 + 128; q++) {
        float e = __expf(sx[q * SMX_STR + tc] - m);
        sx[q * SMX_STR + tc] = e;
        s += e;
    }
    red[t] = s;
    __syncthreads();
    if (t < 64) red[t] = (red[t] + red[64 + t]) + (red[128 + t] + red[192 + t]);
    __syncthreads();
    float inv = 1.f / red[tc];
#pragma unroll 8
    for (int q = tq * 128; q < tq * 128 + 128; q++)
        base[(long)q * NS + tc] = sx[q * SMX_STR + tc] * inv;
}

// ---------------------------------------------------------------- reset counters
__global__ void k_rst() { g_gc[threadIdx.x] = 0; }

// ---------------------------------------------------------------- batch-grouped persistent GRU
// 128 CTAs = 8 groups x 16 CTAs. Group g owns batches 8g..8g+7.
// CTA owns 32 units x 3 gates = 96 Wh rows, pre-swizzled tf32 A-fragments in SMEM.
// release/acquire counter protocol (no full membar on the step critical path).
#define HSTR 516
#define WS_U32 (6 * 64 * 32 * 4)
#define GRU_SMEM ((WS_U32 + 8 * HSTR + 96 * 11) * 4)

__global__ __launch_bounds__(256) void k_gru(const float* __restrict__ GI,
                                             const float* __restrict__ Wh,
                                             const float* __restrict__ bh,
                                             float* __restrict__ Hout) {
    extern __shared__ float sm[];
    u32*   ws = (u32*)sm;
    float* hs = sm + WS_U32;
    float* ps = sm + WS_U32 + 8 * HSTR;
    const u32* hsu = (const u32*)hs;
    u32 hsaddr = cvsm(hs);

    int t = threadIdx.x;
    int w = t >> 5, l = t & 31;
    int r = l >> 2, c = l & 3;
    int grp = blockIdx.x >> 4;
    int cig = blockIdx.x & 15;
    int u0  = cig * 32;
    int bg0 = grp * 8;
    u32* bar = &g_gc[grp * 32];

    for (int idx = t; idx < 6 * 64 * 32; idx += 256) {
        int lane = idx & 31, mtks = idx >> 5;
        int mt = mtks % 6, ks = mtks / 6;
        int rr = lane >> 2, cc = lane & 3;
        int j0 = mt * 16 + rr, j1 = j0 + 8;
        int k0 = ks * 8 + cc, k1 = k0 + 4;
        long row0 = (long)((j0 >> 5) * NA + u0 + (j0 & 31)) * NA;
        long row1 = (long)((j1 >> 5) * NA + u0 + (j1 & 31)) * NA;
        uint4 v;
        v.x = f2tf(Wh[row0 + k0]);
        v.y = f2tf(Wh[row1 + k0]);
        v.z = f2tf(Wh[row0 + k1]);
        v.w = f2tf(Wh[row1 + k1]);
        *(uint4*)&ws[((ks * 6 + mt) * 32 + lane) * 4] = v;
    }

    int cb = t >> 5, cu = t & 31;
    int u = u0 + cu;
    float bhr = bh[u], bhz = bh[NA + u], bhn = bh[2 * NA + u];
    __syncthreads();

    for (int s = 0; s < NS; s++) {
        // GI prefetch (independent of recurrence)
        const float* gi = GI + ((long)s * NB + bg0 + cb) * (3 * NA) + u;
        float gr = __ldg(gi), gz = __ldg(gi + NA), gn = __ldg(gi + 2 * NA);

        // acquire-poll: all 16 group CTAs finished step s-1
        if (s > 0) {
            if (t == 0) {
                u32 need = (u32)(16 * s), v;
                do {
                    asm volatile("ld.acquire.gpu.global.u32 %0,[%1];" : "=r"(v) : "l"(bar));
                } while (v < need);
            }
            __syncthreads();
        }

        // stage h_prev from Hout[s-1] (cp.async, coalesced)
        if (s == 0) {
            float4 zz = make_float4(0.f, 0.f, 0.f, 0.f);
#pragma unroll
            for (int i = 0; i < 4; i++) {
                int g = t + i * 256;
                *(float4*)&hs[(g >> 7) * HSTR + (g & 127) * 4] = zz;
            }
        } else {
            const float* hb = Hout + ((long)(s - 1) * NB + bg0) * NA;
#pragma unroll
            for (int i = 0; i < 4; i++) {
                int g = t + i * 256;
                cpa16(hsaddr + ((g >> 7) * HSTR + (g & 127) * 4) * 4,
                      hb + (g >> 7) * NA + (g & 127) * 4);
            }
            asm volatile("cp.async.commit_group;");
            asm volatile("cp.async.wait_group 0;");
        }
        __syncthreads();

        // mma: warps 0-5, one 16-row m-tile each, N=8, K=512
        if (w < 6) {
            float a0 = 0.f, a1 = 0.f, a2 = 0.f, a3 = 0.f;
#pragma unroll 8
            for (int ks = 0; ks < 64; ks++) {
                uint4 af = *(const uint4*)&ws[((ks * 6 + w) * 32 + l) * 4];
                u32 b0 = hsu[r * HSTR + ks * 8 + c];
                u32 b1 = hsu[r * HSTR + ks * 8 + c + 4];
                asm volatile(
                    "mma.sync.aligned.m16n8k8.row.col.f32.tf32.tf32.f32 "
                    "{%0,%1,%2,%3},{%4,%5,%6,%7},{%8,%9},{%0,%1,%2,%3};"
                    : "+f"(a0), "+f"(a1), "+f"(a2), "+f"(a3)
                    : "r"(af.x), "r"(af.y), "r"(af.z), "r"(af.w),
                      "r"(b0), "r"(b1));
            }
            int row = w * 16 + r;
            ps[row * 11 + c * 2]           = a0;
            ps[row * 11 + c * 2 + 1]       = a1;
            ps[(row + 8) * 11 + c * 2]     = a2;
            ps[(row + 8) * 11 + c * 2 + 1] = a3;
        }
        __syncthreads();

        // gate combine (batch cb, unit cu)
        float ar = ps[cu * 11 + cb];
        float az = ps[(32 + cu) * 11 + cb];
        float an = ps[(64 + cu) * 11 + cb];
        float rg = sigm(gr + ar + bhr);
        float zg = sigm(gz + az + bhz);
        float ng = tanhf(gn + rg * (an + bhn));
        float hp = hs[cb * HSTR + u];
        float hval = (1.f - zg) * ng + zg * hp;
        Hout[((long)s * NB + bg0 + cb) * NA + u] = hval;
        __syncthreads();
        // release-increment: orders this CTA's h stores before counter bump
        if (t == 0)
            asm volatile("red.release.gpu.global.add.u32 [%0],%1;" :: "l"(bar), "r"(1u));
    }
}

// ---------------------------------------------------------------- head
__global__ void k_head(const float* __restrict__ Hs, const float* __restrict__ Wf,
                       const float* __restrict__ bf, float* __restrict__ out) {
    int warp = (blockIdx.x * 256 + threadIdx.x) >> 5;
    int lane = threadIdx.x & 31;
    const float* row = Hs + (long)warp * NA;
    float s = 0.f;
#pragma unroll
    for (int i = 0; i < 16; i++) s += row[lane + i * 32] * __ldg(&Wf[lane + i * 32]);
#pragma unroll
    for (int o = 16; o; o >>= 1) s += __shfl_xor_sync(0xffffffffu, s, o);
    if (lane == 0) {
        int ss = warp >> 6, b = warp & 63;
        out[b * NS + ss] = sigm(s + __ldg(bf));
    }
}

// ---------------------------------------------------------------- launch
extern "C" void kernel_launch(void* const* d_in, const int* in_sizes, int n_in,
                              void* d_out, int out_size) {
    const int*   cate  = (const int*)d_in[0];
    const float* cont  = (const float*)d_in[1];
    const float* emb   = (const float*)d_in[4];
    const float* Wcont = (const float*)d_in[5];
    const float* bcont = (const float*)d_in[6];
    const float* Wcomb = (const float*)d_in[7];
    const float* bcomb = (const float*)d_in[8];
    const float* Wq    = (const float*)d_in[9];
    const float* Wk    = (const float*)d_in[10];
    const float* Wv    = (const float*)d_in[11];
    const float* Wi    = (const float*)d_in[12];
    const float* Wh    = (const float*)d_in[13];
    const float* bi    = (const float*)d_in[14];
    const float* bh    = (const float*)d_in[15];
    const float* Wfin  = (const float*)d_in[16];
    const float* bfin  = (const float*)d_in[17];
    float* out = (float*)d_out;

    float *CE, *X, *Q, *K, *V, *GI;
    cudaGetSymbolAddress((void**)&CE, g_CE);
    cudaGetSymbolAddress((void**)&X,  g_X);
    cudaGetSymbolAddress((void**)&Q,  g_Q);
    cudaGetSymbolAddress((void**)&K,  g_K);
    cudaGetSymbolAddress((void**)&V,  g_V);
    cudaGetSymbolAddress((void**)&GI, g_GI);

    cudaFuncSetAttribute(k_gru, cudaFuncAttributeMaxDynamicSharedMemorySize, GRU_SMEM);
    cudaFuncSetAttribute(k_tgemm<0, 0, 0>, cudaFuncAttributeMaxDynamicSharedMemorySize, GEMM_SMEM);
    cudaFuncSetAttribute(k_tgemm<1, 0, 0>, cudaFuncAttributeMaxDynamicSharedMemorySize, GEMM_SMEM);
    cudaFuncSetAttribute(k_tgemm<0, 1, 1>, cudaFuncAttributeMaxDynamicSharedMemorySize, GEMM_SMEM);
    cudaFuncSetAttribute(k_softmax, cudaFuncAttributeMaxDynamicSharedMemorySize, SMX_SMEM);

    const long SB2 = (long)NS * NS;
    const float iscl = 0.0441941738241592f; // 1/sqrt(512)

    k_prep<<<2, 256>>>(Wcont, bcont, Wcomb, bcomb);
    // x = gather(emb, cate) @ Wcomb[0:512]  + extras fused into epilogue
    k_tgemm<0, 1, 1><<<dim3(4, 256, 1), 256, GEMM_SMEM>>>(
        nullptr, Wcomb, X, NH, NH, 0, 0, 0, NH, nullptr, 1.f, cate, emb, cont);
    // QKV
    k_tgemm<0, 0, 0><<<dim3(4, 256, 1), 256, GEMM_SMEM>>>(
        X, Wq, Q, NA, NH, 0, 0, 0, NA, nullptr, 1.f, nullptr, nullptr, nullptr);
    k_tgemm<0, 0, 0><<<dim3(4, 256, 1), 256, GEMM_SMEM>>>(
        X, Wk, K, NA, NH, 0, 0, 0, NA, nullptr, 1.f, nullptr, nullptr, nullptr);
    k_tgemm<0, 0, 0><<<dim3(4, 256, 1), 256, GEMM_SMEM>>>(
        X, Wv, V, NA, NH, 0, 0, 0, NA, nullptr, 1.f, nullptr, nullptr, nullptr);
    // scores = Q @ K^T / sqrt(A)
    k_tgemm<1, 0, 0><<<dim3(4, 4, 64), 256, GEMM_SMEM>>>(
        Q, K, CE, NS, NA, SB2, SB2, SB2, NS, nullptr, iscl, nullptr, nullptr, nullptr);
    k_softmax<<<dim3(8, 64), 256, SMX_SMEM>>>(CE);
    // Zt[(s,b),:] = (P @ V)[b,s,:]  — transpose fused via ldc/sC
    k_tgemm<0, 0, 0><<<dim3(4, 4, 64), 256, GEMM_SMEM>>>(
        CE, V, Q, NA, NS, SB2, SB2, (long)NA, (long)NB * NA, nullptr, 1.f,
        nullptr, nullptr, nullptr);
    // layer 0
    k_tgemm<1, 0, 0><<<dim3(12, 256, 1), 256, GEMM_SMEM>>>(
        Q, Wi, GI, 3 * NA, NA, 0, 0, 0, 3 * NA, bi, 1.f, nullptr, nullptr, nullptr);
    k_rst<<<1, 256>>>();
    k_gru<<<128, 256, GRU_SMEM>>>(GI, Wh, bh, K);
    // layer 1
    k_tgemm<1, 0, 0><<<dim3(12, 256, 1), 256, GEMM_SMEM>>>(
        K, Wi + 3 * NA * NA, GI, 3 * NA, NA, 0, 0, 0, 3 * NA, bi + 3 * NA, 1.f,
        nullptr, nullptr, nullptr);
    k_rst<<<1, 256>>>();
    k_gru<<<128, 256, GRU_SMEM>>>(GI, Wh + 3 * NA * NA, bh + 3 * NA, V);
    // head
    k_head<<<BS / 8, 256>>>(V, Wfin, bfin, out);
}

// round 14
// speedup vs baseline: 1.2077x; 1.0742x over previous
#include <cuda_runtime.h>
#include <cuda_bf16.h>
#include <math.h>

typedef unsigned long long ull;
typedef unsigned int u32;
typedef __nv_bfloat16 bf16;

// ---------------------------------------------------------------- constants
#define NB   64
#define NS   512
#define NH   512
#define NA   512
#define NCC  4
#define NV   1000
#define NED  128
#define NFF  6
#define BS   32768          // NB*NS

// ---------------------------------------------------------------- scratch
__device__ float g_CE[BS * NH];       // fp32 attention scores
__device__ float g_GI[BS * 3 * NA];   // GRU input gates (per layer), fp32
__device__ float g_K [BS * NA];       // H0 (layer-0 output) fp32
__device__ float g_V [BS * NA];       // H1 (layer-1 output) fp32
__device__ bf16  g_Xb [BS * NH];      // x (bf16)
__device__ bf16  g_Qb [BS * NA];
__device__ bf16  g_Kb [BS * NA];
__device__ bf16  g_Vb [BS * NA];
__device__ bf16  g_Pb [BS * NS];      // softmax probs (bf16)
__device__ bf16  g_Ztb[BS * NA];      // Zt (bf16)
__device__ bf16  g_H0b[BS * NA];      // H0 shadow (bf16)
__device__ bf16  g_Wqb[NH * NA];
__device__ bf16  g_Wkb[NH * NA];
__device__ bf16  g_Wvb[NH * NA];
__device__ bf16  g_Wib[2 * 3 * NA * NA];
__device__ float g_Wcc[NFF * NH];
__device__ float g_bcc[NH];
__device__ u32   g_gc[256];           // per-group arrival counters (stride 32)

// ---------------------------------------------------------------- helpers
__device__ __forceinline__ float sigm(float x) { return 1.f / (1.f + expf(-x)); }
__device__ __forceinline__ u32 f2tf(float x) {
    u32 r; asm("cvt.rna.tf32.f32 %0,%1;" : "=r"(r) : "f"(x)); return r;
}
__device__ __forceinline__ u32 pkbf(float lo, float hi) {
    u32 r; asm("cvt.rn.bf16x2.f32 %0,%1,%2;" : "=r"(r) : "f"(hi), "f"(lo)); return r;
}
__device__ __forceinline__ void cpa16(u32 dst, const void* src) {
    asm volatile("cp.async.cg.shared.global [%0], [%1], 16;" :: "r"(dst), "l"(src));
}
__device__ __forceinline__ u32 cvsm(const void* p) {
    u32 r;
    asm("{ .reg .u64 t; cvta.to.shared.u64 t, %1; cvt.u32.u64 %0, t; }" : "=r"(r) : "l"(p));
    return r;
}

// ---------------------------------------------------------------- prep
__global__ void k_prep(const float* __restrict__ Wcont, const float* __restrict__ bcont,
                       const float* __restrict__ Wcomb, const float* __restrict__ bcomb) {
    int j = blockIdx.x * 256 + threadIdx.x;
    if (j >= NH) return;
    float acc[NFF];
#pragma unroll
    for (int f = 0; f < NFF; f++) acc[f] = 0.f;
    float bacc = bcomb[j];
    for (int m = 0; m < NH; m++) {
        float w2 = Wcomb[(NH + m) * NH + j];
        bacc += bcont[m] * w2;
#pragma unroll
        for (int f = 0; f < NFF; f++) acc[f] += Wcont[f * NH + m] * w2;
    }
#pragma unroll
    for (int f = 0; f < NFF; f++) g_Wcc[f * NH + j] = acc[f];
    g_bcc[j] = bacc;
}

// ---------------------------------------------------------------- fp32 -> bf16 convert
__global__ void k_cvt(const float4* __restrict__ src, uint2* __restrict__ dst, int n4) {
    int i = blockIdx.x * 256 + threadIdx.x;
    if (i >= n4) return;
    float4 v = src[i];
    dst[i] = make_uint2(pkbf(v.x, v.y), pkbf(v.z, v.w));
}

// ---------------------------------------------------------------- combine GEMM (tf32, gather+extras, bf16 out)
#define ASZ 4608
#define BSZ 4608
#define STGSZ (ASZ + BSZ)
#define GEMM_SMEM (3 * STGSZ * 4)

__device__ __forceinline__ void t_load_stage(
    u32 smb, int st, const float* Bm, const int* cate, const float* emb,
    int m0, int n0, int k0, int N, int K, int t) {
    u32 ab = smb + st * (STGSZ * 4);
#pragma unroll
    for (int rr = 0; rr < 4; rr++) {
        int q = t + rr * 256;
        int m = q >> 3, kc = q & 7;
        int k = k0 + kc * 4;
        int cf = k >> 7, e = k & 127;
        int idx = __ldg(cate + (m0 + m) * NCC + cf);
        const float* src = emb + ((long)cf * NV + idx) * NED + e;
        cpa16(ab + (m * 36 + kc * 4) * 4, src);
    }
    u32 bb = ab + ASZ * 4;
#pragma unroll
    for (int rr = 0; rr < 4; rr++) {
        int q = t + rr * 256;
        int k = q >> 5, nc = q & 31;
        cpa16(bb + (k * 136 + nc * 4) * 4, Bm + (long)(k0 + k) * N + n0 + nc * 4);
    }
}

__global__ __launch_bounds__(256, 2) void k_tgemm(
    const float* __restrict__ Bm, bf16* __restrict__ C,
    int N, int K, long ldc,
    const int* __restrict__ cate, const float* __restrict__ emb,
    const float* __restrict__ cont) {
    extern __shared__ u32 smp[];
    u32 smb = cvsm(smp);

    int m0 = blockIdx.y * 128, n0 = blockIdx.x * 128;
    int t = threadIdx.x;
    int warp = t >> 5, lane = t & 31;
    int wm = (warp >> 2) * 64;
    int wn = (warp & 3) * 32;
    int r = lane >> 2, c = lane & 3;
    int la = lane & 15, lh = lane >> 4;

    float acc[4][4][4];
#pragma unroll
    for (int mt = 0; mt < 4; mt++)
#pragma unroll
        for (int nt = 0; nt < 4; nt++)
#pragma unroll
            for (int i = 0; i < 4; i++) acc[mt][nt][i] = 0.f;

    int niter = K >> 5;
    t_load_stage(smb, 0, Bm, cate, emb, m0, n0, 0, N, K, t);
    asm volatile("cp.async.commit_group;");
    t_load_stage(smb, 1, Bm, cate, emb, m0, n0, 32, N, K, t);
    asm volatile("cp.async.commit_group;");

    for (int i = 0; i < niter; i++) {
        if (i == niter - 1) asm volatile("cp.async.wait_group 0;");
        else                asm volatile("cp.async.wait_group 1;");
        __syncthreads();
        if (i + 2 < niter) {
            t_load_stage(smb, (i + 2) % 3, Bm, cate, emb, m0, n0, (i + 2) * 32, N, K, t);
            asm volatile("cp.async.commit_group;");
        }
        u32 As_base = smb + (u32)((i % 3) * STGSZ * 4);
        const u32* Bs_ = smp + (i % 3) * STGSZ + ASZ;
#pragma unroll
        for (int kb = 0; kb < 32; kb += 8) {
            u32 a[4][4];
#pragma unroll
            for (int mt = 0; mt < 4; mt++) {
                u32 aaddr = As_base + (u32)(((wm + mt * 16 + la) * 36 + kb + lh * 4) * 4);
                asm volatile(
                    "ldmatrix.sync.aligned.m8n8.x4.shared.b16 {%0,%1,%2,%3},[%4];"
                    : "=r"(a[mt][0]), "=r"(a[mt][1]), "=r"(a[mt][2]), "=r"(a[mt][3])
                    : "r"(aaddr));
            }
#pragma unroll
            for (int nt = 0; nt < 4; nt++) {
                int col = wn + nt * 8 + r;
                u32 b0 = Bs_[(kb + c) * 136 + col];
                u32 b1 = Bs_[(kb + c + 4) * 136 + col];
#pragma unroll
                for (int mt = 0; mt < 4; mt++) {
                    asm volatile(
                        "mma.sync.aligned.m16n8k8.row.col.f32.tf32.tf32.f32 "
                        "{%0,%1,%2,%3},{%4,%5,%6,%7},{%8,%9},{%0,%1,%2,%3};"
                        : "+f"(acc[mt][nt][0]), "+f"(acc[mt][nt][1]),
                          "+f"(acc[mt][nt][2]), "+f"(acc[mt][nt][3])
                        : "r"(a[mt][0]), "r"(a[mt][1]), "r"(a[mt][2]), "r"(a[mt][3]),
                          "r"(b0), "r"(b1));
                }
            }
        }
    }
#pragma unroll
    for (int mt = 0; mt < 4; mt++) {
#pragma unroll
        for (int nt = 0; nt < 4; nt++) {
            int row = m0 + wm + mt * 16 + r;
            int col = n0 + wn + nt * 8 + c * 2;
            float lox = acc[mt][nt][0], loy = acc[mt][nt][1];
            float hix = acc[mt][nt][2], hiy = acc[mt][nt][3];
            // extras: pos-enc + cont@Wcc + bcc
            int sr0 = row & 511, sr1 = (row + 8) & 511;
            float kf = expf(-(float)col * 0.0179889460f);   // ln(10000)/512
            float s0, c0, s1, c1;
            sincosf((float)sr0 * kf, &s0, &c0);
            sincosf((float)sr1 * kf, &s1, &c1);
            float bc0 = g_bcc[col], bc1 = g_bcc[col + 1];
            float ct0 = 0.f, ct1 = 0.f, ct0b = 0.f, ct1b = 0.f;
#pragma unroll
            for (int f = 0; f < NFF; f++) {
                float w0 = g_Wcc[f * NH + col], w1 = g_Wcc[f * NH + col + 1];
                float cr0 = __ldg(cont + (long)row * NFF + f);
                float cr1 = __ldg(cont + (long)(row + 8) * NFF + f);
                ct0 += cr0 * w0;  ct1 += cr0 * w1;
                ct0b += cr1 * w0; ct1b += cr1 * w1;
            }
            lox += bc0 + ct0 + s0;  loy += bc1 + ct1 + c0;
            hix += bc0 + ct0b + s1; hiy += bc1 + ct1b + c1;
            *(u32*)(C + (long)row * ldc + col)       = pkbf(lox, loy);
            *(u32*)(C + (long)(row + 8) * ldc + col) = pkbf(hix, hiy);
        }
    }
}

// ---------------------------------------------------------------- bf16 GEMM, 128x128 tile, m16n8k16
// TRB=0: B[K,N]; TRB=1: B[N,K]. OUTBF: bf16 C else fp32. ldc in elements.
#define BAS 2560                 // 128 rows * 20 u32 (80B stride)
#define BBS 2560                 // max(32*68, 128*20)
#define BSTG (BAS + BBS)         // 5120 u32 = 20480 B
#define BG_SMEM (3 * BSTG * 4)

template <int TRB>
__device__ __forceinline__ void b_load_stage(
    u32 smb, int st, const bf16* A, const bf16* B,
    int m0, int n0, int k0, int N, int K, int t) {
    u32 ab = smb + st * (BSTG * 4);
#pragma unroll
    for (int rr = 0; rr < 2; rr++) {
        int q = t + rr * 256;
        int m = q >> 2, kc = q & 3;
        cpa16(ab + m * 80 + kc * 16, A + (long)(m0 + m) * K + k0 + kc * 8);
    }
    u32 bb = ab + BAS * 4;
#pragma unroll
    for (int rr = 0; rr < 2; rr++) {
        int q = t + rr * 256;
        if (TRB == 0) {
            int k = q >> 4, nc = q & 15;
            cpa16(bb + k * 272 + nc * 16, B + (long)(k0 + k) * N + n0 + nc * 8);
        } else {
            int n = q >> 2, kc = q & 3;
            cpa16(bb + n * 80 + kc * 16, B + (long)(n0 + n) * K + k0 + kc * 8);
        }
    }
}

template <int TRB, int OUTBF>
__global__ __launch_bounds__(256, 2) void k_bgemm(
    const bf16* __restrict__ A, const bf16* __restrict__ B, void* __restrict__ Cv,
    int N, int K, long sA, long sB, long sC, long ldc,
    const float* __restrict__ bias, float scale) {
    extern __shared__ u32 smp[];
    u32 smb = cvsm(smp);

    A += (long)blockIdx.z * sA;
    B += (long)blockIdx.z * sB;
    int m0 = blockIdx.y * 128, n0 = blockIdx.x * 128;
    int t = threadIdx.x;
    int warp = t >> 5, lane = t & 31;
    int wm = (warp >> 2) * 64;
    int wn = (warp & 3) * 32;
    int r = lane >> 2, c = lane & 3;
    int la = lane & 15, lh = lane >> 4;
    int l15 = lane & 15;

    float acc[4][4][4];
#pragma unroll
    for (int mt = 0; mt < 4; mt++)
#pragma unroll
        for (int nt = 0; nt < 4; nt++)
#pragma unroll
            for (int i = 0; i < 4; i++) acc[mt][nt][i] = 0.f;

    int niter = K >> 5;
    b_load_stage<TRB>(smb, 0, A, B, m0, n0, 0, N, K, t);
    asm volatile("cp.async.commit_group;");
    b_load_stage<TRB>(smb, 1, A, B, m0, n0, 32, N, K, t);
    asm volatile("cp.async.commit_group;");

    for (int i = 0; i < niter; i++) {
        if (i == niter - 1) asm volatile("cp.async.wait_group 0;");
        else                asm volatile("cp.async.wait_group 1;");
        __syncthreads();
        if (i + 2 < niter) {
            b_load_stage<TRB>(smb, (i + 2) % 3, A, B, m0, n0, (i + 2) * 32, N, K, t);
            asm volatile("cp.async.commit_group;");
        }
        u32 As_base = smb + (u32)((i % 3) * BSTG * 4);
        u32 Bs_base = As_base + BAS * 4;
#pragma unroll
        for (int kb = 0; kb < 32; kb += 16) {
            u32 a[4][4];
#pragma unroll
            for (int mt = 0; mt < 4; mt++) {
                u32 aaddr = As_base + (u32)((wm + mt * 16 + la) * 80 + kb * 2 + lh * 16);
                asm volatile(
                    "ldmatrix.sync.aligned.m8n8.x4.shared.b16 {%0,%1,%2,%3},[%4];"
                    : "=r"(a[mt][0]), "=r"(a[mt][1]), "=r"(a[mt][2]), "=r"(a[mt][3])
                    : "r"(aaddr));
            }
#pragma unroll
            for (int nt = 0; nt < 4; nt++) {
                u32 b0, b1;
                if (TRB == 0) {
                    u32 baddr = Bs_base +
                        (u32)((kb + (l15 & 7) + ((l15 >> 3) & 1) * 8) * 272 +
                              (wn + nt * 8) * 2);
                    asm volatile(
                        "ldmatrix.sync.aligned.m8n8.x2.trans.shared.b16 {%0,%1},[%2];"
                        : "=r"(b0), "=r"(b1) : "r"(baddr));
                } else {
                    u32 baddr = Bs_base +
                        (u32)((wn + nt * 8 + (l15 & 7)) * 80 + kb * 2 +
                              ((l15 >> 3) & 1) * 16);
                    asm volatile(
                        "ldmatrix.sync.aligned.m8n8.x2.shared.b16 {%0,%1},[%2];"
                        : "=r"(b0), "=r"(b1) : "r"(baddr));
                }
#pragma unroll
                for (int mt = 0; mt < 4; mt++) {
                    asm volatile(
                        "mma.sync.aligned.m16n8k16.row.col.f32.bf16.bf16.f32 "
                        "{%0,%1,%2,%3},{%4,%5,%6,%7},{%8,%9},{%0,%1,%2,%3};"
                        : "+f"(acc[mt][nt][0]), "+f"(acc[mt][nt][1]),
                          "+f"(acc[mt][nt][2]), "+f"(acc[mt][nt][3])
                        : "r"(a[mt][0]), "r"(a[mt][1]), "r"(a[mt][2]), "r"(a[mt][3]),
                          "r"(b0), "r"(b1));
                }
            }
        }
    }
#pragma unroll
    for (int mt = 0; mt < 4; mt++) {
#pragma unroll
        for (int nt = 0; nt < 4; nt++) {
            int row = m0 + wm + mt * 16 + r;
            int col = n0 + wn + nt * 8 + c * 2;
            float bb0 = 0.f, bb1 = 0.f;
            if (bias) { bb0 = __ldg(bias + col); bb1 = __ldg(bias + col + 1); }
            float lox = acc[mt][nt][0] * scale + bb0;
            float loy = acc[mt][nt][1] * scale + bb1;
            float hix = acc[mt][nt][2] * scale + bb0;
            float hiy = acc[mt][nt][3] * scale + bb1;
            if (OUTBF) {
                bf16* C = (bf16*)Cv + (long)blockIdx.z * sC;
                *(u32*)(C + (long)row * ldc + col)       = pkbf(lox, loy);
                *(u32*)(C + (long)(row + 8) * ldc + col) = pkbf(hix, hiy);
            } else {
                float* C = (float*)Cv + (long)blockIdx.z * sC;
                *(float2*)(C + (long)row * ldc + col)       = make_float2(lox, loy);
                *(float2*)(C + (long)(row + 8) * ldc + col) = make_float2(hix, hiy);
            }
        }
    }
}

// ---------------------------------------------------------------- softmax over q (axis=1), fp32 in, bf16 out
#define SMX_STR 72
#define SMX_SMEM ((512 * SMX_STR + 256) * 4)

__global__ __launch_bounds__(256) void k_softmax(const float* __restrict__ P,
                                                 bf16* __restrict__ Pb) {
    extern __shared__ float sx[];
    float* red = sx + 512 * SMX_STR;
    int b = blockIdx.y, k0 = blockIdx.x * 64;
    int t = threadIdx.x;
    const float* base = P + (long)b * (NS * NS) + k0;
    bf16* baseb = Pb + (long)b * (NS * NS) + k0;

#pragma unroll
    for (int i = 0; i < 32; i++) {
        int q = i * 16 + (t >> 4), c4 = (t & 15) * 4;
        float4 v = *(const float4*)(base + (long)q * NS + c4);
        *(float4*)&sx[q * SMX_STR + c4] = v;
    }
    __syncthreads();

    int tc = t & 63, tq = t >> 6;
    float m = -1e30f;
#pragma unroll 8
    for (int q = tq * 128; q < tq * 128 + 128; q++) m = fmaxf(m, sx[q * SMX_STR + tc]);
    red[t] = m;
    __syncthreads();
    if (t < 64) red[t] = fmaxf(fmaxf(red[t], red[64 + t]), fmaxf(red[128 + t], red[192 + t]));
    __syncthreads();
    m = red[tc];
    __syncthreads();
    float s = 0.f;
#pragma unroll 8
    for (int q = tq * 128; q < tq * 128 + 128; q++) {
        float e = __expf(sx[q * SMX_STR + tc] - m);
        sx[q * SMX_STR + tc] = e;
        s += e;
    }
    red[t] = s;
    __syncthreads();
    if (t < 64) red[t] = (red[t] + red[64 + t]) + (red[128 + t] + red[192 + t]);
    __syncthreads();
    float inv = 1.f / red[tc];
#pragma unroll 8
    for (int q = tq * 128; q < tq * 128 + 128; q++)
        baseb[(long)q * NS + tc] = __float2bfloat16(sx[q * SMX_STR + tc] * inv);
}

// ---------------------------------------------------------------- reset counters
__global__ void k_rst() { g_gc[threadIdx.x] = 0; }

// ---------------------------------------------------------------- batch-grouped persistent GRU (tf32)
#define HSTR 516
#define WS_U32 (6 * 64 * 32 * 4)
#define GRU_SMEM ((WS_U32 + 8 * HSTR + 96 * 11) * 4)

__global__ __launch_bounds__(256) void k_gru(const float* __restrict__ GI,
                                             const float* __restrict__ Wh,
                                             const float* __restrict__ bh,
                                             float* __restrict__ Hout,
                                             bf16* __restrict__ Hb) {
    extern __shared__ float sm[];
    u32*   ws = (u32*)sm;
    float* hs = sm + WS_U32;
    float* ps = sm + WS_U32 + 8 * HSTR;
    const u32* hsu = (const u32*)hs;
    u32 hsaddr = cvsm(hs);

    int t = threadIdx.x;
    int w = t >> 5, l = t & 31;
    int r = l >> 2, c = l & 3;
    int grp = blockIdx.x >> 4;
    int cig = blockIdx.x & 15;
    int u0  = cig * 32;
    int bg0 = grp * 8;
    u32* bar = &g_gc[grp * 32];

    for (int idx = t; idx < 6 * 64 * 32; idx += 256) {
        int lane = idx & 31, mtks = idx >> 5;
        int mt = mtks % 6, ks = mtks / 6;
        int rr = lane >> 2, cc = lane & 3;
        int j0 = mt * 16 + rr, j1 = j0 + 8;
        int k0 = ks * 8 + cc, k1 = k0 + 4;
        long row0 = (long)((j0 >> 5) * NA + u0 + (j0 & 31)) * NA;
        long row1 = (long)((j1 >> 5) * NA + u0 + (j1 & 31)) * NA;
        uint4 v;
        v.x = f2tf(Wh[row0 + k0]);
        v.y = f2tf(Wh[row1 + k0]);
        v.z = f2tf(Wh[row0 + k1]);
        v.w = f2tf(Wh[row1 + k1]);
        *(uint4*)&ws[((ks * 6 + mt) * 32 + lane) * 4] = v;
    }

    int cb = t >> 5, cu = t & 31;
    int u = u0 + cu;
    float bhr = bh[u], bhz = bh[NA + u], bhn = bh[2 * NA + u];
    __syncthreads();

    for (int s = 0; s < NS; s++) {
        const float* gi = GI + ((long)s * NB + bg0 + cb) * (3 * NA) + u;
        float gr = __ldg(gi), gz = __ldg(gi + NA), gn = __ldg(gi + 2 * NA);

        if (s > 0) {
            if (t == 0) {
                u32 need = (u32)(16 * s), v;
                do {
                    asm volatile("ld.acquire.gpu.global.u32 %0,[%1];" : "=r"(v) : "l"(bar));
                } while (v < need);
            }
            __syncthreads();
        }

        if (s == 0) {
            float4 zz = make_float4(0.f, 0.f, 0.f, 0.f);
#pragma unroll
            for (int i = 0; i < 4; i++) {
                int g = t + i * 256;
                *(float4*)&hs[(g >> 7) * HSTR + (g & 127) * 4] = zz;
            }
        } else {
            const float* hb = Hout + ((long)(s - 1) * NB + bg0) * NA;
#pragma unroll
            for (int i = 0; i < 4; i++) {
                int g = t + i * 256;
                cpa16(hsaddr + ((g >> 7) * HSTR + (g & 127) * 4) * 4,
                      hb + (g >> 7) * NA + (g & 127) * 4);
            }
            asm volatile("cp.async.commit_group;");
            asm volatile("cp.async.wait_group 0;");
        }
        __syncthreads();

        if (w < 6) {
            float a0 = 0.f, a1 = 0.f, a2 = 0.f, a3 = 0.f;
#pragma unroll 8
            for (int ks = 0; ks < 64; ks++) {
                uint4 af = *(const uint4*)&ws[((ks * 6 + w) * 32 + l) * 4];
                u32 b0 = hsu[r * HSTR + ks * 8 + c];
                u32 b1 = hsu[r * HSTR + ks * 8 + c + 4];
                asm volatile(
                    "mma.sync.aligned.m16n8k8.row.col.f32.tf32.tf32.f32 "
                    "{%0,%1,%2,%3},{%4,%5,%6,%7},{%8,%9},{%0,%1,%2,%3};"
                    : "+f"(a0), "+f"(a1), "+f"(a2), "+f"(a3)
                    : "r"(af.x), "r"(af.y), "r"(af.z), "r"(af.w),
                      "r"(b0), "r"(b1));
            }
            int row = w * 16 + r;
            ps[row * 11 + c * 2]           = a0;
            ps[row * 11 + c * 2 + 1]       = a1;
            ps[(row + 8) * 11 + c * 2]     = a2;
            ps[(row + 8) * 11 + c * 2 + 1] = a3;
        }
        __syncthreads();

        float ar = ps[cu * 11 + cb];
        float az = ps[(32 + cu) * 11 + cb];
        float an = ps[(64 + cu) * 11 + cb];
        float rg = sigm(gr + ar + bhr);
        float zg = sigm(gz + az + bhz);
        float ng = tanhf(gn + rg * (an + bhn));
        float hp = hs[cb * HSTR + u];
        float hval = (1.f - zg) * ng + zg * hp;
        long oidx = ((long)s * NB + bg0 + cb) * NA + u;
        Hout[oidx] = hval;
        if (Hb) Hb[oidx] = __float2bfloat16(hval);
        __syncthreads();
        if (t == 0)
            asm volatile("red.release.gpu.global.add.u32 [%0],%1;" :: "l"(bar), "r"(1u));
    }
}

// ---------------------------------------------------------------- head
__global__ void k_head(const float* __restrict__ Hs, const float* __restrict__ Wf,
                       const float* __restrict__ bf, float* __restrict__ out) {
    int warp = (blockIdx.x * 256 + threadIdx.x) >> 5;
    int lane = threadIdx.x & 31;
    const float* row = Hs + (long)warp * NA;
    float s = 0.f;
#pragma unroll
    for (int i = 0; i < 16; i++) s += row[lane + i * 32] * __ldg(&Wf[lane + i * 32]);
#pragma unroll
    for (int o = 16; o; o >>= 1) s += __shfl_xor_sync(0xffffffffu, s, o);
    if (lane == 0) {
        int ss = warp >> 6, b = warp & 63;
        out[b * NS + ss] = sigm(s + __ldg(bf));
    }
}

// ---------------------------------------------------------------- launch
extern "C" void kernel_launch(void* const* d_in, const int* in_sizes, int n_in,
                              void* d_out, int out_size) {
    const int*   cate  = (const int*)d_in[0];
    const float* cont  = (const float*)d_in[1];
    const float* emb   = (const float*)d_in[4];
    const float* Wcont = (const float*)d_in[5];
    const float* bcont = (const float*)d_in[6];
    const float* Wcomb = (const float*)d_in[7];
    const float* bcomb = (const float*)d_in[8];
    const float* Wq    = (const float*)d_in[9];
    const float* Wk    = (const float*)d_in[10];
    const float* Wv    = (const float*)d_in[11];
    const float* Wi    = (const float*)d_in[12];
    const float* Wh    = (const float*)d_in[13];
    const float* bi    = (const float*)d_in[14];
    const float* bh    = (const float*)d_in[15];
    const float* Wfin  = (const float*)d_in[16];
    const float* bfin  = (const float*)d_in[17];
    float* out = (float*)d_out;

    float *CE, *GI, *H0, *H1;
    bf16 *Xb, *Qb, *Kb, *Vb, *Pb, *Ztb, *H0b, *Wqb, *Wkb, *Wvb, *Wib;
    cudaGetSymbolAddress((void**)&CE,  g_CE);
    cudaGetSymbolAddress((void**)&GI,  g_GI);
    cudaGetSymbolAddress((void**)&H0,  g_K);
    cudaGetSymbolAddress((void**)&H1,  g_V);
    cudaGetSymbolAddress((void**)&Xb,  g_Xb);
    cudaGetSymbolAddress((void**)&Qb,  g_Qb);
    cudaGetSymbolAddress((void**)&Kb,  g_Kb);
    cudaGetSymbolAddress((void**)&Vb,  g_Vb);
    cudaGetSymbolAddress((void**)&Pb,  g_Pb);
    cudaGetSymbolAddress((void**)&Ztb, g_Ztb);
    cudaGetSymbolAddress((void**)&H0b, g_H0b);
    cudaGetSymbolAddress((void**)&Wqb, g_Wqb);
    cudaGetSymbolAddress((void**)&Wkb, g_Wkb);
    cudaGetSymbolAddress((void**)&Wvb, g_Wvb);
    cudaGetSymbolAddress((void**)&Wib, g_Wib);

    cudaFuncSetAttribute(k_gru, cudaFuncAttributeMaxDynamicSharedMemorySize, GRU_SMEM);
    cudaFuncSetAttribute(k_tgemm, cudaFuncAttributeMaxDynamicSharedMemorySize, GEMM_SMEM);
    cudaFuncSetAttribute(k_bgemm<0, 1>, cudaFuncAttributeMaxDynamicSharedMemorySize, BG_SMEM);
    cudaFuncSetAttribute(k_bgemm<1, 0>, cudaFuncAttributeMaxDynamicSharedMemorySize, BG_SMEM);
    cudaFuncSetAttribute(k_softmax, cudaFuncAttributeMaxDynamicSharedMemorySize, SMX_SMEM);

    const long SB2 = (long)NS * NS;
    const float iscl = 0.0441941738241592f; // 1/sqrt(512)

    k_prep<<<2, 256>>>(Wcont, bcont, Wcomb, bcomb);
    // weight conversions (fp32 -> bf16)
    k_cvt<<<NH * NA / 1024, 256>>>((const float4*)Wq, (uint2*)Wqb, NH * NA / 4);
    k_cvt<<<NH * NA / 1024, 256>>>((const float4*)Wk, (uint2*)Wkb, NH * NA / 4);
    k_cvt<<<NH * NA / 1024, 256>>>((const float4*)Wv, (uint2*)Wvb, NH * NA / 4);
    k_cvt<<<2 * 3 * NA * NA / 1024, 256>>>((const float4*)Wi, (uint2*)Wib,
                                           2 * 3 * NA * NA / 4);
    // x = gather(emb, cate) @ Wcomb[0:512] + extras  (tf32, bf16 out)
    k_tgemm<<<dim3(4, 256, 1), 256, GEMM_SMEM>>>(Wcomb, Xb, NH, NH, NH, cate, emb, cont);
    // QKV (bf16)
    k_bgemm<0, 1><<<dim3(4, 256, 1), 256, BG_SMEM>>>(
        Xb, Wqb, Qb, NA, NH, 0, 0, 0, NA, nullptr, 1.f);
    k_bgemm<0, 1><<<dim3(4, 256, 1), 256, BG_SMEM>>>(
        Xb, Wkb, Kb, NA, NH, 0, 0, 0, NA, nullptr, 1.f);
    k_bgemm<0, 1><<<dim3(4, 256, 1), 256, BG_SMEM>>>(
        Xb, Wvb, Vb, NA, NH, 0, 0, 0, NA, nullptr, 1.f);
    // scores = Q @ K^T / sqrt(A)  (bf16 in, fp32 out)
    k_bgemm<1, 0><<<dim3(4, 4, 64), 256, BG_SMEM>>>(
        Qb, Kb, CE, NS, NA, SB2, SB2, SB2, NS, nullptr, iscl);
    k_softmax<<<dim3(8, 64), 256, SMX_SMEM>>>(CE, Pb);
    // Zt[(s,b),:] = (P @ V)[b,s,:]  (bf16, fused transpose)
    k_bgemm<0, 1><<<dim3(4, 4, 64), 256, BG_SMEM>>>(
        Pb, Vb, Ztb, NA, NS, SB2, SB2, (long)NA, (long)NB * NA, nullptr, 1.f);
    // layer 0
    k_bgemm<1, 0><<<dim3(12, 256, 1), 256, BG_SMEM>>>(
        Ztb, Wib, GI, 3 * NA, NA, 0, 0, 0, 3 * NA, bi, 1.f);
    k_rst<<<1, 256>>>();
    k_gru<<<128, 256, GRU_SMEM>>>(GI, Wh, bh, H0, H0b);
    // layer 1
    k_bgemm<1, 0><<<dim3(12, 256, 1), 256, BG_SMEM>>>(
        H0b, Wib + 3 * NA * NA, GI, 3 * NA, NA, 0, 0, 0, 3 * NA, bi + 3 * NA, 1.f);
    k_rst<<<1, 256>>>();
    k_gru<<<128, 256, GRU_SMEM>>>(GI, Wh + 3 * NA * NA, bh + 3 * NA, H1, nullptr);
    // head
    k_head<<<BS / 8, 256>>>(H1, Wfin, bfin, out);
}

// round 15
// speedup vs baseline: 1.5550x; 1.2876x over previous
#include <cuda_runtime.h>
#include <cuda_bf16.h>
#include <math.h>

typedef unsigned long long ull;
typedef unsigned int u32;
typedef __nv_bfloat16 bf16;

// ---------------------------------------------------------------- constants
#define NB   64
#define NS   512
#define NH   512
#define NA   512
#define NCC  4
#define NV   1000
#define NED  128
#define NFF  6
#define BS   32768          // NB*NS

// ---------------------------------------------------------------- scratch
__device__ float g_CE[BS * NH];       // fp32 attention scores
__device__ float g_GI[BS * 3 * NA];   // GRU input gates (per layer), fp32
__device__ float g_K [BS * NA];       // H0 (layer-0 output) fp32
__device__ float g_V [BS * NA];       // H1 (layer-1 output) fp32
__device__ bf16  g_Xb [BS * NH];      // x (bf16)
__device__ bf16  g_Qb [BS * NA];
__device__ bf16  g_Kb [BS * NA];
__device__ bf16  g_Vb [BS * NA];
__device__ bf16  g_Pb [BS * NS];      // softmax probs (bf16)
__device__ bf16  g_Ztb[BS * NA];      // Zt (bf16)
__device__ bf16  g_H0b[BS * NA];      // H0 shadow (bf16)
__device__ bf16  g_H1b[BS * NA];      // H1 shadow (bf16)
__device__ bf16  g_Wqb[NH * NA];
__device__ bf16  g_Wkb[NH * NA];
__device__ bf16  g_Wvb[NH * NA];
__device__ bf16  g_Wib[2 * 3 * NA * NA];
__device__ float g_Wcc[NFF * NH];
__device__ float g_bcc[NH];
__device__ u32   g_gc[256];           // per-group arrival counters (stride 32)

// ---------------------------------------------------------------- helpers
__device__ __forceinline__ float sigm(float x) { return 1.f / (1.f + expf(-x)); }
__device__ __forceinline__ u32 pkbf(float lo, float hi) {
    u32 r; asm("cvt.rn.bf16x2.f32 %0,%1,%2;" : "=r"(r) : "f"(hi), "f"(lo)); return r;
}
__device__ __forceinline__ void cpa16(u32 dst, const void* src) {
    asm volatile("cp.async.cg.shared.global [%0], [%1], 16;" :: "r"(dst), "l"(src));
}
__device__ __forceinline__ u32 cvsm(const void* p) {
    u32 r;
    asm("{ .reg .u64 t; cvta.to.shared.u64 t, %1; cvt.u32.u64 %0, t; }" : "=r"(r) : "l"(p));
    return r;
}

// ---------------------------------------------------------------- prep
__global__ void k_prep(const float* __restrict__ Wcont, const float* __restrict__ bcont,
                       const float* __restrict__ Wcomb, const float* __restrict__ bcomb) {
    int j = blockIdx.x * 256 + threadIdx.x;
    if (j >= NH) return;
    float acc[NFF];
#pragma unroll
    for (int f = 0; f < NFF; f++) acc[f] = 0.f;
    float bacc = bcomb[j];
    for (int m = 0; m < NH; m++) {
        float w2 = Wcomb[(NH + m) * NH + j];
        bacc += bcont[m] * w2;
#pragma unroll
        for (int f = 0; f < NFF; f++) acc[f] += Wcont[f * NH + m] * w2;
    }
#pragma unroll
    for (int f = 0; f < NFF; f++) g_Wcc[f * NH + j] = acc[f];
    g_bcc[j] = bacc;
}

// ---------------------------------------------------------------- fp32 -> bf16 convert
__global__ void k_cvt(const float4* __restrict__ src, uint2* __restrict__ dst, int n4) {
    int i = blockIdx.x * 256 + threadIdx.x;
    if (i >= n4) return;
    float4 v = src[i];
    dst[i] = make_uint2(pkbf(v.x, v.y), pkbf(v.z, v.w));
}

// ---------------------------------------------------------------- combine GEMM (tf32, gather+extras, bf16 out)
#define ASZ 4608
#define BSZ 4608
#define STGSZ (ASZ + BSZ)
#define GEMM_SMEM (3 * STGSZ * 4)

__device__ __forceinline__ void t_load_stage(
    u32 smb, int st, const float* Bm, const int* cate, const float* emb,
    int m0, int n0, int k0, int N, int K, int t) {
    u32 ab = smb + st * (STGSZ * 4);
#pragma unroll
    for (int rr = 0; rr < 4; rr++) {
        int q = t + rr * 256;
        int m = q >> 3, kc = q & 7;
        int k = k0 + kc * 4;
        int cf = k >> 7, e = k & 127;
        int idx = __ldg(cate + (m0 + m) * NCC + cf);
        const float* src = emb + ((long)cf * NV + idx) * NED + e;
        cpa16(ab + (m * 36 + kc * 4) * 4, src);
    }
    u32 bb = ab + ASZ * 4;
#pragma unroll
    for (int rr = 0; rr < 4; rr++) {
        int q = t + rr * 256;
        int k = q >> 5, nc = q & 31;
        cpa16(bb + (k * 136 + nc * 4) * 4, Bm + (long)(k0 + k) * N + n0 + nc * 4);
    }
}

__global__ __launch_bounds__(256, 2) void k_tgemm(
    const float* __restrict__ Bm, bf16* __restrict__ C,
    int N, int K, long ldc,
    const int* __restrict__ cate, const float* __restrict__ emb,
    const float* __restrict__ cont) {
    extern __shared__ u32 smp[];
    u32 smb = cvsm(smp);

    int m0 = blockIdx.y * 128, n0 = blockIdx.x * 128;
    int t = threadIdx.x;
    int warp = t >> 5, lane = t & 31;
    int wm = (warp >> 2) * 64;
    int wn = (warp & 3) * 32;
    int r = lane >> 2, c = lane & 3;
    int la = lane & 15, lh = lane >> 4;

    float acc[4][4][4];
#pragma unroll
    for (int mt = 0; mt < 4; mt++)
#pragma unroll
        for (int nt = 0; nt < 4; nt++)
#pragma unroll
            for (int i = 0; i < 4; i++) acc[mt][nt][i] = 0.f;

    int niter = K >> 5;
    t_load_stage(smb, 0, Bm, cate, emb, m0, n0, 0, N, K, t);
    asm volatile("cp.async.commit_group;");
    t_load_stage(smb, 1, Bm, cate, emb, m0, n0, 32, N, K, t);
    asm volatile("cp.async.commit_group;");

    for (int i = 0; i < niter; i++) {
        if (i == niter - 1) asm volatile("cp.async.wait_group 0;");
        else                asm volatile("cp.async.wait_group 1;");
        __syncthreads();
        if (i + 2 < niter) {
            t_load_stage(smb, (i + 2) % 3, Bm, cate, emb, m0, n0, (i + 2) * 32, N, K, t);
            asm volatile("cp.async.commit_group;");
        }
        u32 As_base = smb + (u32)((i % 3) * STGSZ * 4);
        const u32* Bs_ = smp + (i % 3) * STGSZ + ASZ;
#pragma unroll
        for (int kb = 0; kb < 32; kb += 8) {
            u32 a[4][4];
#pragma unroll
            for (int mt = 0; mt < 4; mt++) {
                u32 aaddr = As_base + (u32)(((wm + mt * 16 + la) * 36 + kb + lh * 4) * 4);
                asm volatile(
                    "ldmatrix.sync.aligned.m8n8.x4.shared.b16 {%0,%1,%2,%3},[%4];"
                    : "=r"(a[mt][0]), "=r"(a[mt][1]), "=r"(a[mt][2]), "=r"(a[mt][3])
                    : "r"(aaddr));
            }
#pragma unroll
            for (int nt = 0; nt < 4; nt++) {
                int col = wn + nt * 8 + r;
                u32 b0 = Bs_[(kb + c) * 136 + col];
                u32 b1 = Bs_[(kb + c + 4) * 136 + col];
#pragma unroll
                for (int mt = 0; mt < 4; mt++) {
                    asm volatile(
                        "mma.sync.aligned.m16n8k8.row.col.f32.tf32.tf32.f32 "
                        "{%0,%1,%2,%3},{%4,%5,%6,%7},{%8,%9},{%0,%1,%2,%3};"
                        : "+f"(acc[mt][nt][0]), "+f"(acc[mt][nt][1]),
                          "+f"(acc[mt][nt][2]), "+f"(acc[mt][nt][3])
                        : "r"(a[mt][0]), "r"(a[mt][1]), "r"(a[mt][2]), "r"(a[mt][3]),
                          "r"(b0), "r"(b1));
                }
            }
        }
    }
#pragma unroll
    for (int mt = 0; mt < 4; mt++) {
#pragma unroll
        for (int nt = 0; nt < 4; nt++) {
            int row = m0 + wm + mt * 16 + r;
            int col = n0 + wn + nt * 8 + c * 2;
            float lox = acc[mt][nt][0], loy = acc[mt][nt][1];
            float hix = acc[mt][nt][2], hiy = acc[mt][nt][3];
            int sr0 = row & 511, sr1 = (row + 8) & 511;
            float kf = expf(-(float)col * 0.0179889460f);   // ln(10000)/512
            float s0, c0, s1, c1;
            sincosf((float)sr0 * kf, &s0, &c0);
            sincosf((float)sr1 * kf, &s1, &c1);
            float bc0 = g_bcc[col], bc1 = g_bcc[col + 1];
            float ct0 = 0.f, ct1 = 0.f, ct0b = 0.f, ct1b = 0.f;
#pragma unroll
            for (int f = 0; f < NFF; f++) {
                float w0 = g_Wcc[f * NH + col], w1 = g_Wcc[f * NH + col + 1];
                float cr0 = __ldg(cont + (long)row * NFF + f);
                float cr1 = __ldg(cont + (long)(row + 8) * NFF + f);
                ct0 += cr0 * w0;  ct1 += cr0 * w1;
                ct0b += cr1 * w0; ct1b += cr1 * w1;
            }
            lox += bc0 + ct0 + s0;  loy += bc1 + ct1 + c0;
            hix += bc0 + ct0b + s1; hiy += bc1 + ct1b + c1;
            *(u32*)(C + (long)row * ldc + col)       = pkbf(lox, loy);
            *(u32*)(C + (long)(row + 8) * ldc + col) = pkbf(hix, hiy);
        }
    }
}

// ---------------------------------------------------------------- bf16 GEMM, 128x128 tile, m16n8k16
#define BAS 2560
#define BBS 2560
#define BSTG (BAS + BBS)
#define BG_SMEM (3 * BSTG * 4)

template <int TRB>
__device__ __forceinline__ void b_load_stage(
    u32 smb, int st, const bf16* A, const bf16* B,
    int m0, int n0, int k0, int N, int K, int t) {
    u32 ab = smb + st * (BSTG * 4);
#pragma unroll
    for (int rr = 0; rr < 2; rr++) {
        int q = t + rr * 256;
        int m = q >> 2, kc = q & 3;
        cpa16(ab + m * 80 + kc * 16, A + (long)(m0 + m) * K + k0 + kc * 8);
    }
    u32 bb = ab + BAS * 4;
#pragma unroll
    for (int rr = 0; rr < 2; rr++) {
        int q = t + rr * 256;
        if (TRB == 0) {
            int k = q >> 4, nc = q & 15;
            cpa16(bb + k * 272 + nc * 16, B + (long)(k0 + k) * N + n0 + nc * 8);
        } else {
            int n = q >> 2, kc = q & 3;
            cpa16(bb + n * 80 + kc * 16, B + (long)(n0 + n) * K + k0 + kc * 8);
        }
    }
}

template <int TRB, int OUTBF>
__global__ __launch_bounds__(256, 2) void k_bgemm(
    const bf16* __restrict__ A, const bf16* __restrict__ B, void* __restrict__ Cv,
    int N, int K, long sA, long sB, long sC, long ldc,
    const float* __restrict__ bias, float scale) {
    extern __shared__ u32 smp[];
    u32 smb = cvsm(smp);

    A += (long)blockIdx.z * sA;
    B += (long)blockIdx.z * sB;
    int m0 = blockIdx.y * 128, n0 = blockIdx.x * 128;
    int t = threadIdx.x;
    int warp = t >> 5, lane = t & 31;
    int wm = (warp >> 2) * 64;
    int wn = (warp & 3) * 32;
    int r = lane >> 2, c = lane & 3;
    int la = lane & 15, lh = lane >> 4;
    int l15 = lane & 15;

    float acc[4][4][4];
#pragma unroll
    for (int mt = 0; mt < 4; mt++)
#pragma unroll
        for (int nt = 0; nt < 4; nt++)
#pragma unroll
            for (int i = 0; i < 4; i++) acc[mt][nt][i] = 0.f;

    int niter = K >> 5;
    b_load_stage<TRB>(smb, 0, A, B, m0, n0, 0, N, K, t);
    asm volatile("cp.async.commit_group;");
    b_load_stage<TRB>(smb, 1, A, B, m0, n0, 32, N, K, t);
    asm volatile("cp.async.commit_group;");

    for (int i = 0; i < niter; i++) {
        if (i == niter - 1) asm volatile("cp.async.wait_group 0;");
        else                asm volatile("cp.async.wait_group 1;");
        __syncthreads();
        if (i + 2 < niter) {
            b_load_stage<TRB>(smb, (i + 2) % 3, A, B, m0, n0, (i + 2) * 32, N, K, t);
            asm volatile("cp.async.commit_group;");
        }
        u32 As_base = smb + (u32)((i % 3) * BSTG * 4);
        u32 Bs_base = As_base + BAS * 4;
#pragma unroll
        for (int kb = 0; kb < 32; kb += 16) {
            u32 a[4][4];
#pragma unroll
            for (int mt = 0; mt < 4; mt++) {
                u32 aaddr = As_base + (u32)((wm + mt * 16 + la) * 80 + kb * 2 + lh * 16);
                asm volatile(
                    "ldmatrix.sync.aligned.m8n8.x4.shared.b16 {%0,%1,%2,%3},[%4];"
                    : "=r"(a[mt][0]), "=r"(a[mt][1]), "=r"(a[mt][2]), "=r"(a[mt][3])
                    : "r"(aaddr));
            }
#pragma unroll
            for (int nt = 0; nt < 4; nt++) {
                u32 b0, b1;
                if (TRB == 0) {
                    u32 baddr = Bs_base +
                        (u32)((kb + (l15 & 7) + ((l15 >> 3) & 1) * 8) * 272 +
                              (wn + nt * 8) * 2);
                    asm volatile(
                        "ldmatrix.sync.aligned.m8n8.x2.trans.shared.b16 {%0,%1},[%2];"
                        : "=r"(b0), "=r"(b1) : "r"(baddr));
                } else {
                    u32 baddr = Bs_base +
                        (u32)((wn + nt * 8 + (l15 & 7)) * 80 + kb * 2 +
                              ((l15 >> 3) & 1) * 16);
                    asm volatile(
                        "ldmatrix.sync.aligned.m8n8.x2.shared.b16 {%0,%1},[%2];"
                        : "=r"(b0), "=r"(b1) : "r"(baddr));
                }
#pragma unroll
                for (int mt = 0; mt < 4; mt++) {
                    asm volatile(
                        "mma.sync.aligned.m16n8k16.row.col.f32.bf16.bf16.f32 "
                        "{%0,%1,%2,%3},{%4,%5,%6,%7},{%8,%9},{%0,%1,%2,%3};"
                        : "+f"(acc[mt][nt][0]), "+f"(acc[mt][nt][1]),
                          "+f"(acc[mt][nt][2]), "+f"(acc[mt][nt][3])
                        : "r"(a[mt][0]), "r"(a[mt][1]), "r"(a[mt][2]), "r"(a[mt][3]),
                          "r"(b0), "r"(b1));
                }
            }
        }
    }
#pragma unroll
    for (int mt = 0; mt < 4; mt++) {
#pragma unroll
        for (int nt = 0; nt < 4; nt++) {
            int row = m0 + wm + mt * 16 + r;
            int col = n0 + wn + nt * 8 + c * 2;
            float bb0 = 0.f, bb1 = 0.f;
            if (bias) { bb0 = __ldg(bias + col); bb1 = __ldg(bias + col + 1); }
            float lox = acc[mt][nt][0] * scale + bb0;
            float loy = acc[mt][nt][1] * scale + bb1;
            float hix = acc[mt][nt][2] * scale + bb0;
            float hiy = acc[mt][nt][3] * scale + bb1;
            if (OUTBF) {
                bf16* C = (bf16*)Cv + (long)blockIdx.z * sC;
                *(u32*)(C + (long)row * ldc + col)       = pkbf(lox, loy);
                *(u32*)(C + (long)(row + 8) * ldc + col) = pkbf(hix, hiy);
            } else {
                float* C = (float*)Cv + (long)blockIdx.z * sC;
                *(float2*)(C + (long)row * ldc + col)       = make_float2(lox, loy);
                *(float2*)(C + (long)(row + 8) * ldc + col) = make_float2(hix, hiy);
            }
        }
    }
}

// ---------------------------------------------------------------- softmax over q (axis=1), fp32 in, bf16 out
#define SMX_STR 72
#define SMX_SMEM ((512 * SMX_STR + 256) * 4)

__global__ __launch_bounds__(256) void k_softmax(const float* __restrict__ P,
                                                 bf16* __restrict__ Pb) {
    extern __shared__ float sx[];
    float* red = sx + 512 * SMX_STR;
    int b = blockIdx.y, k0 = blockIdx.x * 64;
    int t = threadIdx.x;
    const float* base = P + (long)b * (NS * NS) + k0;
    bf16* baseb = Pb + (long)b * (NS * NS) + k0;

#pragma unroll
    for (int i = 0; i < 32; i++) {
        int q = i * 16 + (t >> 4), c4 = (t & 15) * 4;
        float4 v = *(const float4*)(base + (long)q * NS + c4);
        *(float4*)&sx[q * SMX_STR + c4] = v;
    }
    __syncthreads();

    int tc = t & 63, tq = t >> 6;
    float m = -1e30f;
#pragma unroll 8
    for (int q = tq * 128; q < tq * 128 + 128; q++) m = fmaxf(m, sx[q * SMX_STR + tc]);
    red[t] = m;
    __syncthreads();
    if (t < 64) red[t] = fmaxf(fmaxf(red[t], red[64 + t]), fmaxf(red[128 + t], red[192 + t]));
    __syncthreads();
    m = red[tc];
    __syncthreads();
    float s = 0.f;
#pragma unroll 8
    for (int q = tq * 128; q < tq * 128 + 128; q++) {
        float e = __expf(sx[q * SMX_STR + tc] - m);
        sx[q * SMX_STR + tc] = e;
        s += e;
    }
    red[t] = s;
    __syncthreads();
    if (t < 64) red[t] = (red[t] + red[64 + t]) + (red[128 + t] + red[192 + t]);
    __syncthreads();
    float inv = 1.f / red[tc];
#pragma unroll 8
    for (int q = tq * 128; q < tq * 128 + 128; q++)
        baseb[(long)q * NS + tc] = __float2bfloat16(sx[q * SMX_STR + tc] * inv);
}

// ---------------------------------------------------------------- reset counters
__global__ void k_rst() { g_gc[threadIdx.x] = 0; }

// ---------------------------------------------------------------- batch-grouped persistent GRU (bf16 mma)
// 128 CTAs = 8 groups x 16 CTAs. Group owns 8 batches; CTA owns 32 units x 3 gates = 96 rows.
// Wh pre-swizzled as m16n8k16 bf16 A-fragments (96KB). h staged bf16 from Hb shadow.
// hp (z*h term) read fp32 from Hout. release/acquire counter sync.
#define HS2 260                       // u32 stride of staged h row (520 bf16)
#define WSB_U32 (6 * 32 * 32 * 4)     // 24576 u32 = 96KB
#define GRU_SMEM ((WSB_U32 + 8 * HS2 + 96 * 11) * 4)   // 110,848 B

__global__ __launch_bounds__(256) void k_gru(const float* __restrict__ GI,
                                             const float* __restrict__ Wh,
                                             const float* __restrict__ bh,
                                             float* __restrict__ Hout,
                                             bf16* __restrict__ Hb) {
    extern __shared__ u32 smu[];
    u32* ws = smu;
    u32* hsu = smu + WSB_U32;                 // staged h (bf16), [8][260] u32
    float* ps = (float*)(smu + WSB_U32 + 8 * HS2);
    u32 hsaddr = cvsm(hsu);

    int t = threadIdx.x;
    int w = t >> 5, l = t & 31;
    int r = l >> 2, c = l & 3;
    int grp = blockIdx.x >> 4;
    int cig = blockIdx.x & 15;
    int u0  = cig * 32;
    int bg0 = grp * 8;
    u32* bar = &g_gc[grp * 32];

    // ---- build bf16 Wh fragments: rows j 0..95: gate=j>>5, unit=u0+(j&31)
    for (int idx = t; idx < 6 * 32 * 32; idx += 256) {
        int lane = idx & 31, mtks = idx >> 5;
        int mt = mtks % 6, ks = mtks / 6;       // ks 0..31
        int rr = lane >> 2, cc = lane & 3;
        int j0 = mt * 16 + rr, j1 = j0 + 8;
        long row0 = (long)((j0 >> 5) * NA + u0 + (j0 & 31)) * NA;
        long row1 = (long)((j1 >> 5) * NA + u0 + (j1 & 31)) * NA;
        int k0 = ks * 16 + 2 * cc;
        uint4 v;
        v.x = pkbf(Wh[row0 + k0],     Wh[row0 + k0 + 1]);
        v.y = pkbf(Wh[row1 + k0],     Wh[row1 + k0 + 1]);
        v.z = pkbf(Wh[row0 + k0 + 8], Wh[row0 + k0 + 9]);
        v.w = pkbf(Wh[row1 + k0 + 8], Wh[row1 + k0 + 9]);
        *(uint4*)&ws[((ks * 6 + mt) * 32 + lane) * 4] = v;
    }

    int cb = t >> 5, cu = t & 31;
    int u = u0 + cu;
    float bhr = bh[u], bhz = bh[NA + u], bhn = bh[2 * NA + u];
    __syncthreads();

    for (int s = 0; s < NS; s++) {
        // GI prefetch (independent of recurrence)
        const float* gi = GI + ((long)s * NB + bg0 + cb) * (3 * NA) + u;
        float gr = __ldg(gi), gz = __ldg(gi + NA), gn = __ldg(gi + 2 * NA);

        // acquire-poll for step s-1 completion
        if (s > 0) {
            if (t == 0) {
                u32 need = (u32)(16 * s), v;
                do {
                    asm volatile("ld.acquire.gpu.global.u32 %0,[%1];" : "=r"(v) : "l"(bar));
                } while (v < need);
            }
            __syncthreads();
        }

        // stage h_prev (bf16) + fp32 hp load
        float hp = 0.f;
        if (s == 0) {
            uint4 zz = make_uint4(0, 0, 0, 0);
#pragma unroll
            for (int i = 0; i < 2; i++) {
                int g = t + i * 256;
                *(uint4*)&hsu[(g >> 6) * HS2 + (g & 63) * 4] = zz;
            }
        } else {
            const bf16* hb = Hb + ((long)(s - 1) * NB + bg0) * NA;
#pragma unroll
            for (int i = 0; i < 2; i++) {
                int g = t + i * 256;
                cpa16(hsaddr + ((g >> 6) * HS2 + (g & 63) * 4) * 4,
                      hb + (g >> 6) * NA + (g & 63) * 8);
            }
            hp = __ldg(&Hout[((long)(s - 1) * NB + bg0 + cb) * NA + u]);
            asm volatile("cp.async.commit_group;");
            asm volatile("cp.async.wait_group 0;");
        }
        __syncthreads();

        // mma: warps 0-5, one 16-row m-tile each, N=8, K=512 (bf16 m16n8k16)
        if (w < 6) {
            float a0 = 0.f, a1 = 0.f, a2 = 0.f, a3 = 0.f;
#pragma unroll 8
            for (int ks = 0; ks < 32; ks++) {
                uint4 af = *(const uint4*)&ws[((ks * 6 + w) * 32 + l) * 4];
                u32 b0 = hsu[r * HS2 + ks * 8 + c];
                u32 b1 = hsu[r * HS2 + ks * 8 + c + 4];
                asm volatile(
                    "mma.sync.aligned.m16n8k16.row.col.f32.bf16.bf16.f32 "
                    "{%0,%1,%2,%3},{%4,%5,%6,%7},{%8,%9},{%0,%1,%2,%3};"
                    : "+f"(a0), "+f"(a1), "+f"(a2), "+f"(a3)
                    : "r"(af.x), "r"(af.y), "r"(af.z), "r"(af.w),
                      "r"(b0), "r"(b1));
            }
            int row = w * 16 + r;
            ps[row * 11 + c * 2]           = a0;
            ps[row * 11 + c * 2 + 1]       = a1;
            ps[(row + 8) * 11 + c * 2]     = a2;
            ps[(row + 8) * 11 + c * 2 + 1] = a3;
        }
        __syncthreads();

        // gate combine (batch cb, unit cu)
        float ar = ps[cu * 11 + cb];
        float az = ps[(32 + cu) * 11 + cb];
        float an = ps[(64 + cu) * 11 + cb];
        float rg = sigm(gr + ar + bhr);
        float zg = sigm(gz + az + bhz);
        float ng = tanhf(gn + rg * (an + bhn));
        float hval = (1.f - zg) * ng + zg * hp;
        long oidx = ((long)s * NB + bg0 + cb) * NA + u;
        Hout[oidx] = hval;
        Hb[oidx] = __float2bfloat16(hval);
        __syncthreads();
        if (t == 0)
            asm volatile("red.release.gpu.global.add.u32 [%0],%1;" :: "l"(bar), "r"(1u));
    }
}

// ---------------------------------------------------------------- head
__global__ void k_head(const float* __restrict__ Hs, const float* __restrict__ Wf,
                       const float* __restrict__ bf, float* __restrict__ out) {
    int warp = (blockIdx.x * 256 + threadIdx.x) >> 5;
    int lane = threadIdx.x & 31;
    const float* row = Hs + (long)warp * NA;
    float s = 0.f;
#pragma unroll
    for (int i = 0; i < 16; i++) s += row[lane + i * 32] * __ldg(&Wf[lane + i * 32]);
#pragma unroll
    for (int o = 16; o; o >>= 1) s += __shfl_xor_sync(0xffffffffu, s, o);
    if (lane == 0) {
        int ss = warp >> 6, b = warp & 63;
        out[b * NS + ss] = sigm(s + __ldg(bf));
    }
}

// ---------------------------------------------------------------- launch
extern "C" void kernel_launch(void* const* d_in, const int* in_sizes, int n_in,
                              void* d_out, int out_size) {
    const int*   cate  = (const int*)d_in[0];
    const float* cont  = (const float*)d_in[1];
    const float* emb   = (const float*)d_in[4];
    const float* Wcont = (const float*)d_in[5];
    const float* bcont = (const float*)d_in[6];
    const float* Wcomb = (const float*)d_in[7];
    const float* bcomb = (const float*)d_in[8];
    const float* Wq    = (const float*)d_in[9];
    const float* Wk    = (const float*)d_in[10];
    const float* Wv    = (const float*)d_in[11];
    const float* Wi    = (const float*)d_in[12];
    const float* Wh    = (const float*)d_in[13];
    const float* bi    = (const float*)d_in[14];
    const float* bh    = (const float*)d_in[15];
    const float* Wfin  = (const float*)d_in[16];
    const float* bfin  = (const float*)d_in[17];
    float* out = (float*)d_out;

    float *CE, *GI, *H0, *H1;
    bf16 *Xb, *Qb, *Kb, *Vb, *Pb, *Ztb, *H0b, *H1b, *Wqb, *Wkb, *Wvb, *Wib;
    cudaGetSymbolAddress((void**)&CE,  g_CE);
    cudaGetSymbolAddress((void**)&GI,  g_GI);
    cudaGetSymbolAddress((void**)&H0,  g_K);
    cudaGetSymbolAddress((void**)&H1,  g_V);
    cudaGetSymbolAddress((void**)&Xb,  g_Xb);
    cudaGetSymbolAddress((void**)&Qb,  g_Qb);
    cudaGetSymbolAddress((void**)&Kb,  g_Kb);
    cudaGetSymbolAddress((void**)&Vb,  g_Vb);
    cudaGetSymbolAddress((void**)&Pb,  g_Pb);
    cudaGetSymbolAddress((void**)&Ztb, g_Ztb);
    cudaGetSymbolAddress((void**)&H0b, g_H0b);
    cudaGetSymbolAddress((void**)&H1b, g_H1b);
    cudaGetSymbolAddress((void**)&Wqb, g_Wqb);
    cudaGetSymbolAddress((void**)&Wkb, g_Wkb);
    cudaGetSymbolAddress((void**)&Wvb, g_Wvb);
    cudaGetSymbolAddress((void**)&Wib, g_Wib);

    cudaFuncSetAttribute(k_gru, cudaFuncAttributeMaxDynamicSharedMemorySize, GRU_SMEM);
    cudaFuncSetAttribute(k_tgemm, cudaFuncAttributeMaxDynamicSharedMemorySize, GEMM_SMEM);
    cudaFuncSetAttribute(k_bgemm<0, 1>, cudaFuncAttributeMaxDynamicSharedMemorySize, BG_SMEM);
    cudaFuncSetAttribute(k_bgemm<1, 0>, cudaFuncAttributeMaxDynamicSharedMemorySize, BG_SMEM);
    cudaFuncSetAttribute(k_softmax, cudaFuncAttributeMaxDynamicSharedMemorySize, SMX_SMEM);

    const long SB2 = (long)NS * NS;
    const float iscl = 0.0441941738241592f; // 1/sqrt(512)

    k_prep<<<2, 256>>>(Wcont, bcont, Wcomb, bcomb);
    k_cvt<<<NH * NA / 1024, 256>>>((const float4*)Wq, (uint2*)Wqb, NH * NA / 4);
    k_cvt<<<NH * NA / 1024, 256>>>((const float4*)Wk, (uint2*)Wkb, NH * NA / 4);
    k_cvt<<<NH * NA / 1024, 256>>>((const float4*)Wv, (uint2*)Wvb, NH * NA / 4);
    k_cvt<<<2 * 3 * NA * NA / 1024, 256>>>((const float4*)Wi, (uint2*)Wib,
                                           2 * 3 * NA * NA / 4);
    // x = gather(emb, cate) @ Wcomb[0:512] + extras  (tf32, bf16 out)
    k_tgemm<<<dim3(4, 256, 1), 256, GEMM_SMEM>>>(Wcomb, Xb, NH, NH, NH, cate, emb, cont);
    // QKV (bf16)
    k_bgemm<0, 1><<<dim3(4, 256, 1), 256, BG_SMEM>>>(
        Xb, Wqb, Qb, NA, NH, 0, 0, 0, NA, nullptr, 1.f);
    k_bgemm<0, 1><<<dim3(4, 256, 1), 256, BG_SMEM>>>(
        Xb, Wkb, Kb, NA, NH, 0, 0, 0, NA, nullptr, 1.f);
    k_bgemm<0, 1><<<dim3(4, 256, 1), 256, BG_SMEM>>>(
        Xb, Wvb, Vb, NA, NH, 0, 0, 0, NA, nullptr, 1.f);
    // scores = Q @ K^T / sqrt(A)  (bf16 in, fp32 out)
    k_bgemm<1, 0><<<dim3(4, 4, 64), 256, BG_SMEM>>>(
        Qb, Kb, CE, NS, NA, SB2, SB2, SB2, NS, nullptr, iscl);
    k_softmax<<<dim3(8, 64), 256, SMX_SMEM>>>(CE, Pb);
    // Zt[(s,b),:] = (P @ V)[b,s,:]  (bf16, fused transpose)
    k_bgemm<0, 1><<<dim3(4, 4, 64), 256, BG_SMEM>>>(
        Pb, Vb, Ztb, NA, NS, SB2, SB2, (long)NA, (long)NB * NA, nullptr, 1.f);
    // layer 0
    k_bgemm<1, 0><<<dim3(12, 256, 1), 256, BG_SMEM>>>(
        Ztb, Wib, GI, 3 * NA, NA, 0, 0, 0, 3 * NA, bi, 1.f);
    k_rst<<<1, 256>>>();
    k_gru<<<128, 256, GRU_SMEM>>>(GI, Wh, bh, H0, H0b);
    // layer 1
    k_bgemm<1, 0><<<dim3(12, 256, 1), 256, BG_SMEM>>>(
        H0b, Wib + 3 * NA * NA, GI, 3 * NA, NA, 0, 0, 0, 3 * NA, bi + 3 * NA, 1.f);
    k_rst<<<1, 256>>>();
    k_gru<<<128, 256, GRU_SMEM>>>(GI, Wh + 3 * NA * NA, bh + 3 * NA, H1, H1b);
    // head
    k_head<<<BS / 8, 256>>>(H1, Wfin, bfin, out);
}